// round 10
// baseline (speedup 1.0000x reference)
#include <cuda_runtime.h>

#define L_ 2048
#define E_ 256
#define H2_ 256
#define H4_ 1024
#define T_ 6
#define START_ 4
#define STOP_ 5
#define NEG_ (-10000.0f)
#define NEGI_ (-1.0e30f)

// Scratch (static __device__ arrays: allocation-free per harness rules)
__device__ float g_pre[2][L_][H4_];    // 16 MB: input projections per direction
__device__ float g_h[2][L_][H2_];      // 4 MB: hidden states (position-indexed)
__device__ float g_feats[L_][T_];      // 48 KB: emission scores
__device__ float g_mats[64][40];       // CRF chunk matrices (6x6, padded)

__device__ __forceinline__ void fma2(unsigned long long& d,
                                     unsigned long long a, unsigned long long b) {
    asm("fma.rn.f32x2 %0, %1, %2, %0;" : "+l"(d) : "l"(a), "l"(b));
}
__device__ __forceinline__ float lo32(unsigned long long v) {
    return __uint_as_float((unsigned)(v & 0xffffffffull));
}
__device__ __forceinline__ float hi32(unsigned long long v) {
    return __uint_as_float((unsigned)(v >> 32));
}
__device__ __forceinline__ void mbar_wait(unsigned addr, unsigned ph) {
    unsigned done = 0;
    do {
        asm volatile("{\n\t.reg .pred p;\n\t"
            "mbarrier.try_wait.parity.acquire.cluster.shared::cta.b64 p, [%1], %2, 0x989680;\n\t"
            "selp.b32 %0, 1, 0, p;\n\t}"
            : "=r"(done) : "r"(addr), "r"(ph) : "memory");
    } while (!done);
}

// ---------------------------------------------------------------------------
// Kernel 1: pre[d][t][n] = sum_k embed[sent[t']][k] * Wih_d[n][k] + bih[n] + bhh[n]
// ---------------------------------------------------------------------------
__global__ __launch_bounds__(256) void gemm_pre_kernel(
    const int* __restrict__ sent, const float* __restrict__ embed,
    const float* __restrict__ WihF, const float* __restrict__ bihF, const float* __restrict__ bhhF,
    const float* __restrict__ WihB, const float* __restrict__ bihB, const float* __restrict__ bhhB)
{
    const int d = blockIdx.z;
    const float* __restrict__ Wih = d ? WihB : WihF;
    const float* __restrict__ bih = d ? bihB : bihF;
    const float* __restrict__ bhh = d ? bhhB : bhhF;

    __shared__ __align__(16) float As[16][64];   // [k][m]
    __shared__ __align__(16) float Bs[16][64];   // [k][n]

    const int t0 = blockIdx.x * 64;
    const int n0 = blockIdx.y * 64;
    const int tid = threadIdx.x;
    const int tm = (tid & 15) * 4;
    const int tn = (tid >> 4) * 4;
    const int am = tid >> 2;         // 0..63
    const int ak = (tid & 3) * 4;    // 0,4,8,12

    const int tg = t0 + am;
    const int tp = d ? (L_ - 1 - tg) : tg;
    const float* arow = embed + (size_t)sent[tp] * E_;
    const float* brow = Wih + (size_t)(n0 + am) * E_;

    unsigned long long acc2[4][2];
    #pragma unroll
    for (int i = 0; i < 4; i++) { acc2[i][0] = 0ull; acc2[i][1] = 0ull; }

    for (int k0 = 0; k0 < E_; k0 += 16) {
        float4 av = *(const float4*)(arow + k0 + ak);
        float4 bv = *(const float4*)(brow + k0 + ak);
        __syncthreads();
        As[ak + 0][am] = av.x; As[ak + 1][am] = av.y;
        As[ak + 2][am] = av.z; As[ak + 3][am] = av.w;
        Bs[ak + 0][am] = bv.x; Bs[ak + 1][am] = bv.y;
        Bs[ak + 2][am] = bv.z; Bs[ak + 3][am] = bv.w;
        __syncthreads();
        #pragma unroll
        for (int kk = 0; kk < 16; kk++) {
            float a4[4];
            *(float4*)a4 = *(const float4*)&As[kk][tm];
            ulonglong2 b2 = *(const ulonglong2*)&Bs[kk][tn];
            #pragma unroll
            for (int i = 0; i < 4; i++) {
                unsigned long long asp;
                asm("mov.b64 %0, {%1, %1};" : "=l"(asp) : "f"(a4[i]));
                fma2(acc2[i][0], asp, b2.x);
                fma2(acc2[i][1], asp, b2.y);
            }
        }
    }
    #pragma unroll
    for (int i = 0; i < 4; i++) {
        float r[4] = { lo32(acc2[i][0]), hi32(acc2[i][0]),
                       lo32(acc2[i][1]), hi32(acc2[i][1]) };
        #pragma unroll
        for (int j = 0; j < 4; j++) {
            int n = n0 + tn + j;
            g_pre[d][t0 + tm + i][n] = r[j] + bih[n] + bhh[n];
        }
    }
}

// ---------------------------------------------------------------------------
// Kernel 2: LSTM recurrence, 8-CTA cluster per direction.
// Round-7 structure with ONE change: the per-step h broadcast is aggregated.
// Each warp's lane 0 stages its 4 h-values in smem; after __syncthreads +
// fence.proxy.async, warp 0 lanes 0..7 issue ONE 128-byte cp.async.bulk
// (CTA->peer-CTA smem) per destination with complete_tx on the peer barrier.
// Arrivals per barrier per phase: 8 bulk completions (was 64 st.async txs);
// expect_tx stays 8 x 128 B = 1024 B.
// Staging reuse is race-free: our wait at step t transitively requires every
// peer's bulk read of our step-(t-2) staging to have completed.
// ---------------------------------------------------------------------------
__global__ void __cluster_dims__(8, 1, 1) __launch_bounds__(256, 1)
lstm_kernel(const float* __restrict__ WhhF, const float* __restrict__ WhhB,
            const float* __restrict__ h0, const float* __restrict__ c0)
{
    __shared__ __align__(16) float h_sm[2][H2_];
    __shared__ __align__(16) float stg[2][32];   // staging: this CTA's 32 h
    __shared__ __align__(8) unsigned long long mbar[2];

    const int d = blockIdx.y;
    unsigned rank;
    asm("mov.u32 %0, %%cluster_ctarank;" : "=r"(rank));

    const int tid = threadIdx.x;
    const int w = tid >> 5;          // warp 0..7
    const int l = tid & 31;          // lane
    const int ri = l >> 1;           // row-in-warp 0..15
    const int half = l & 1;          // column half
    const int q = ri >> 2;           // gate: 0=i 1=f 2=g 3=o
    const int i4 = ri & 3;           // element within warp's 4 h-values
    const int grow = q * 256 + (int)rank * 32 + w * 4 + i4;   // global W row
    const float* __restrict__ Whh = d ? WhhB : WhhF;

    // Weights: 128 floats per thread = 64 packed f32x2 register pairs
    unsigned long long w2[64];
    {
        const float* wrow = Whh + (size_t)grow * H2_ + half * 128;
        #pragma unroll
        for (int i = 0; i < 32; i++) {
            ulonglong2 v = *(const ulonglong2*)(wrow + 4 * i);
            w2[2 * i] = v.x; w2[2 * i + 1] = v.y;
        }
    }

    const unsigned mb0 = (unsigned)__cvta_generic_to_shared(&mbar[0]);
    const unsigned mb1 = (unsigned)__cvta_generic_to_shared(&mbar[1]);
    if (tid == 0) {
        asm volatile("mbarrier.init.shared.b64 [%0], %1;" :: "r"(mb0), "r"(1) : "memory");
        asm volatile("mbarrier.init.shared.b64 [%0], %1;" :: "r"(mb1), "r"(1) : "memory");
        // pre-post phase 0 of both barriers (stores from steps 0 and 1)
        asm volatile("mbarrier.arrive.expect_tx.shared.b64 _, [%0], %1;" :: "r"(mb1), "r"(1024) : "memory");
        asm volatile("mbarrier.arrive.expect_tx.shared.b64 _, [%0], %1;" :: "r"(mb0), "r"(1024) : "memory");
    }
    h_sm[0][tid] = h0[d * H2_ + tid];
    const int hbase = (int)rank * 32 + w * 4;
    float cst = c0[d * H2_ + hbase + ((l >> 1) & 3)];
    __syncthreads();
    // barrier init + pre-posts must be cluster-visible before any peer bulk
    asm volatile("barrier.cluster.arrive.aligned;" ::: "memory");
    asm volatile("barrier.cluster.wait.aligned;"   ::: "memory");

    const float* __restrict__ pre = &g_pre[d][0][0];
    const unsigned hsm_base = (unsigned)__cvta_generic_to_shared(&h_sm[0][0]);
    const unsigned stg_base = (unsigned)__cvta_generic_to_shared(&stg[0][0]);
    const float two_or_one = (q == 2) ? 2.f : 1.f;
    unsigned ph0 = 0, ph1 = 0;

    // hoisted per-lane remote addresses (dest CTA = l&7; ops predicated l<8)
    const int dl = l & 7;
    // dest = peer h_sm[buffer][rank*32] (128 bytes per CTA slice)
    unsigned da0, da1, rb0, rb1;
    asm("mapa.shared::cluster.u32 %0, %1, %2;"
        : "=r"(da0) : "r"(hsm_base + 0u   + rank * 128u), "r"(dl));
    asm("mapa.shared::cluster.u32 %0, %1, %2;"
        : "=r"(da1) : "r"(hsm_base + 1024u + rank * 128u), "r"(dl));
    asm("mapa.shared::cluster.u32 %0, %1, %2;" : "=r"(rb0) : "r"(mb0), "r"(dl));
    asm("mapa.shared::cluster.u32 %0, %1, %2;" : "=r"(rb1) : "r"(mb1), "r"(dl));
    const unsigned sa0 = stg_base;          // staging for even dest buffer
    const unsigned sa1 = stg_base + 128u;   // staging for odd dest buffer

    for (int t = 0; t < L_; t++) {
        const int buf = t & 1;
        // prefetch input projection before blocking on the wait
        float p = __ldg(pre + (size_t)t * H4_ + grow);

        if (t > 0) {
            if (buf) { mbar_wait(mb1, ph1); ph1 ^= 1; }
            else     { mbar_wait(mb0, ph0); ph0 ^= 1; }
            // repost the barrier just consumed for its next use (step t+2)
            if (w == 0 && l == 0 && t <= L_ - 3) {
                const unsigned mbc = buf ? mb1 : mb0;
                asm volatile("mbarrier.arrive.expect_tx.shared.b64 _, [%0], %1;"
                             :: "r"(mbc), "r"(1024) : "memory");
            }
        }

        const float* hb = h_sm[buf] + half * 128;
        unsigned long long a0 = 0, a1 = 0, a2 = 0, a3 = 0;
        #pragma unroll
        for (int i = 0; i < 16; i++) {
            ulonglong2 hv0 = *(const ulonglong2*)(hb + 8 * i);
            ulonglong2 hv1 = *(const ulonglong2*)(hb + 8 * i + 4);
            fma2(a0, w2[4 * i + 0], hv0.x);
            fma2(a1, w2[4 * i + 1], hv0.y);
            fma2(a2, w2[4 * i + 2], hv1.x);
            fma2(a3, w2[4 * i + 3], hv1.y);
        }
        float s = (lo32(a0) + hi32(a0)) + (lo32(a1) + hi32(a1))
                + (lo32(a2) + hi32(a2)) + (lo32(a3) + hi32(a3));
        s += __shfl_xor_sync(0xffffffffu, s, 1);   // combine halves
        float z = s + p;

        // unified activation: sigmoid for i/f/o, tanh (=2*sig(2z)-1) for g
        float arg = z * two_or_one;
        float sig = 1.f / (1.f + __expf(-arg));
        float act = (q == 2) ? (2.f * sig - 1.f) : sig;

        // gather gate quadruple to the q=0 lanes (l in 0..7)
        float fA = __shfl_sync(0xffffffffu, act, (l + 8) & 31);
        float gA = __shfl_sync(0xffffffffu, act, (l + 16) & 31);
        float oA = __shfl_sync(0xffffffffu, act, (l + 24) & 31);
        cst = fA * cst + act * gA;
        float th = 2.f / (1.f + __expf(-2.f * cst)) - 1.f;
        float h = oA * th;

        // broadcast the warp's 4 h-values to all lanes
        float h0v = __shfl_sync(0xffffffffu, h, 0);
        float h1v = __shfl_sync(0xffffffffu, h, 2);
        float h2v = __shfl_sync(0xffffffffu, h, 4);
        float h3v = __shfl_sync(0xffffffffu, h, 6);

        if (l == 0) {
            // stage into the next-buffer staging slot + global h store
            stg[buf ^ 1][w * 4 + 0] = h0v;
            stg[buf ^ 1][w * 4 + 1] = h1v;
            stg[buf ^ 1][w * 4 + 2] = h2v;
            stg[buf ^ 1][w * 4 + 3] = h3v;
            const int pos = d ? (L_ - 1 - t) : t;
            *(float4*)&g_h[d][pos][hbase] = make_float4(h0v, h1v, h2v, h3v);
        }
        if (t < L_ - 1) {
            __syncthreads();   // staging complete + STS drained
            if (w == 0) {
                asm volatile("fence.proxy.async.shared::cta;" ::: "memory");
                const unsigned da = buf ? da0 : da1;   // next buffer
                const unsigned sa = buf ? sa0 : sa1;
                const unsigned rb = buf ? rb0 : rb1;
                asm volatile("{\n\t.reg .pred p;\n\t"
                    "setp.lt.s32 p, %4, 8;\n\t"
                    "@p cp.async.bulk.shared::cluster.shared::cta.mbarrier::complete_tx::bytes "
                    "[%0], [%1], %2, [%3];\n\t}"
                    :: "r"(da), "r"(sa), "r"(128u), "r"(rb), "r"(l) : "memory");
            }
        }
    }
    // all phases fully consumed by the final waits; plain exit sync
    asm volatile("barrier.cluster.arrive.aligned;" ::: "memory");
    asm volatile("barrier.cluster.wait.aligned;"   ::: "memory");
}

// ---------------------------------------------------------------------------
// Kernel 3: feats[p][tag] = concat(hf[p],hb[p]) . W_out[tag] + b_out[tag]
// ---------------------------------------------------------------------------
__global__ __launch_bounds__(256) void feats_kernel(
    const float* __restrict__ Wout, const float* __restrict__ bout)
{
    const int warp = threadIdx.x >> 5, lane = threadIdx.x & 31;
    const int p = blockIdx.x * 8 + warp;
    float x[16];
    #pragma unroll
    for (int i = 0; i < 8; i++) x[i] = g_h[0][p][lane + 32 * i];
    #pragma unroll
    for (int i = 0; i < 8; i++) x[8 + i] = g_h[1][p][lane + 32 * i];
    #pragma unroll
    for (int tag = 0; tag < T_; tag++) {
        const float* wrow = Wout + tag * (2 * H2_);
        float acc = 0.f;
        #pragma unroll
        for (int i = 0; i < 16; i++)
            acc += x[i] * wrow[(i < 8 ? 0 : 256) + lane + 32 * (i & 7)];
        #pragma unroll
        for (int o = 16; o > 0; o >>= 1) acc += __shfl_xor_sync(0xffffffffu, acc, o);
        if (lane == 0) g_feats[p][tag] = acc + bout[tag];
    }
}

// ---------------------------------------------------------------------------
// Kernel 4a: CRF chunk matrices (log-semiring parallel scan, 64 chunks x 32).
// ---------------------------------------------------------------------------
__global__ __launch_bounds__(256) void crf_chunks_kernel(
    const float* __restrict__ trans)
{
    const int warp = threadIdx.x >> 5, lane = threadIdx.x & 31;
    const int wc = blockIdx.x * 8 + warp;     // chunk id 0..63
    const int ln = (lane < T_) ? lane : 0;    // this lane's "next" state n

    float trr[T_];
    #pragma unroll
    for (int k = 0; k < T_; k++) trr[k] = trans[ln * T_ + k];

    float m[T_];
    #pragma unroll
    for (int p = 0; p < T_; p++) m[p] = (ln == p) ? 0.f : NEGI_;

    const float* ff = &g_feats[wc * 32][0];
    for (int s = 0; s < 32; s++) {
        const float emit = ff[s * T_ + ln];
        #pragma unroll
        for (int p = 0; p < T_; p++) {
            float v0 = __shfl_sync(0xffffffffu, m[p], 0) + trr[0];
            float v1 = __shfl_sync(0xffffffffu, m[p], 1) + trr[1];
            float v2 = __shfl_sync(0xffffffffu, m[p], 2) + trr[2];
            float v3 = __shfl_sync(0xffffffffu, m[p], 3) + trr[3];
            float v4 = __shfl_sync(0xffffffffu, m[p], 4) + trr[4];
            float v5 = __shfl_sync(0xffffffffu, m[p], 5) + trr[5];
            float mx = fmaxf(fmaxf(fmaxf(v0, v1), fmaxf(v2, v3)), fmaxf(v4, v5));
            float sum = __expf(v0 - mx) + __expf(v1 - mx) + __expf(v2 - mx)
                      + __expf(v3 - mx) + __expf(v4 - mx) + __expf(v5 - mx);
            m[p] = mx + __logf(sum) + emit;
        }
    }
    if (lane < T_) {
        #pragma unroll
        for (int p = 0; p < T_; p++) g_mats[wc][lane * T_ + p] = m[p];
    }
}

// ---------------------------------------------------------------------------
// Kernel 4b: gold score + fold 64 chunk matrices into fv, final logsumexp.
// ---------------------------------------------------------------------------
__global__ __launch_bounds__(256) void crf_final_kernel(
    const int* __restrict__ tags, const float* __restrict__ trans,
    float* __restrict__ out)
{
    __shared__ float red[256];
    const int tid = threadIdx.x;

    // gold score
    float g = 0.f;
    for (int i = tid; i < L_; i += 256) {
        int cur = tags[i];
        int prev = (i == 0) ? START_ : tags[i - 1];
        g += trans[cur * T_ + prev] + g_feats[i][cur];
    }
    if (tid == 0) g += trans[STOP_ * T_ + tags[L_ - 1]];
    red[tid] = g;
    __syncthreads();
    for (int s = 128; s > 0; s >>= 1) {
        if (tid < s) red[tid] += red[tid + s];
        __syncthreads();
    }

    if (tid < 32) {
        const int ln = (tid < T_) ? tid : 0;
        float fv = (ln == START_) ? 0.f : NEG_;
        for (int c = 0; c < 64; c++) {
            float r0 = g_mats[c][ln * T_ + 0], r1 = g_mats[c][ln * T_ + 1];
            float r2 = g_mats[c][ln * T_ + 2], r3 = g_mats[c][ln * T_ + 3];
            float r4 = g_mats[c][ln * T_ + 4], r5 = g_mats[c][ln * T_ + 5];
            float v0 = r0 + __shfl_sync(0xffffffffu, fv, 0);
            float v1 = r1 + __shfl_sync(0xffffffffu, fv, 1);
            float v2 = r2 + __shfl_sync(0xffffffffu, fv, 2);
            float v3 = r3 + __shfl_sync(0xffffffffu, fv, 3);
            float v4 = r4 + __shfl_sync(0xffffffffu, fv, 4);
            float v5 = r5 + __shfl_sync(0xffffffffu, fv, 5);
            float mx = fmaxf(fmaxf(fmaxf(v0, v1), fmaxf(v2, v3)), fmaxf(v4, v5));
            float sum = __expf(v0 - mx) + __expf(v1 - mx) + __expf(v2 - mx)
                      + __expf(v3 - mx) + __expf(v4 - mx) + __expf(v5 - mx);
            fv = mx + __logf(sum);
        }
        // final: logsumexp(fv + trans[STOP])
        float v = fv + trans[STOP_ * T_ + ln];
        if (tid >= T_) v = NEGI_;
        float mx = v;
        #pragma unroll
        for (int o = 4; o > 0; o >>= 1) mx = fmaxf(mx, __shfl_xor_sync(0xffu, mx, o));
        mx = __shfl_sync(0xffffffffu, mx, 0);
        float e = (tid < T_) ? __expf(v - mx) : 0.f;
        #pragma unroll
        for (int o = 4; o > 0; o >>= 1) e += __shfl_xor_sync(0xffu, e, o);
        if (tid == 0) out[0] = mx + __logf(e) - red[0];
    }
}

// ---------------------------------------------------------------------------
extern "C" void kernel_launch(void* const* d_in, const int* in_sizes, int n_in,
                              void* d_out, int out_size)
{
    const int*   sentence = (const int*)d_in[0];
    const int*   tags     = (const int*)d_in[1];
    const float* embed    = (const float*)d_in[2];
    const float* Wih_f    = (const float*)d_in[3];
    const float* Whh_f    = (const float*)d_in[4];
    const float* bih_f    = (const float*)d_in[5];
    const float* bhh_f    = (const float*)d_in[6];
    const float* Wih_b    = (const float*)d_in[7];
    const float* Whh_b    = (const float*)d_in[8];
    const float* bih_b    = (const float*)d_in[9];
    const float* bhh_b    = (const float*)d_in[10];
    const float* h0       = (const float*)d_in[11];
    const float* c0       = (const float*)d_in[12];
    const float* W_out    = (const float*)d_in[13];
    const float* b_out    = (const float*)d_in[14];
    const float* trans    = (const float*)d_in[15];
    float* out = (float*)d_out;

    gemm_pre_kernel<<<dim3(L_ / 64, H4_ / 64, 2), 256>>>(
        sentence, embed, Wih_f, bih_f, bhh_f, Wih_b, bih_b, bhh_b);
    lstm_kernel<<<dim3(8, 2), 256>>>(Whh_f, Whh_b, h0, c0);
    feats_kernel<<<L_ / 8, 256>>>(W_out, b_out);
    crf_chunks_kernel<<<8, 256>>>(trans);
    crf_final_kernel<<<1, 256>>>(tags, trans, out);
}

// round 11
// speedup vs baseline: 1.2296x; 1.2296x over previous
#include <cuda_runtime.h>

#define L_ 2048
#define E_ 256
#define H2_ 256
#define H4_ 1024
#define T_ 6
#define START_ 4
#define STOP_ 5
#define NEG_ (-10000.0f)
#define NEGI_ (-1.0e30f)
#define NCHUNK_ 128
#define CLEN_ (L_ / NCHUNK_)   // 16

// Scratch (static __device__ arrays: allocation-free per harness rules)
__device__ float g_pre[2][L_][H4_];    // 16 MB: input projections per direction
__device__ float g_h[2][L_][H2_];      // 4 MB: hidden states (position-indexed)
__device__ float g_feats[L_][T_];      // 48 KB: emission scores
__device__ float g_mats[NCHUNK_][40];  // CRF chunk matrices (6x6, padded)

__device__ __forceinline__ void fma2(unsigned long long& d,
                                     unsigned long long a, unsigned long long b) {
    asm("fma.rn.f32x2 %0, %1, %2, %0;" : "+l"(d) : "l"(a), "l"(b));
}
__device__ __forceinline__ float lo32(unsigned long long v) {
    return __uint_as_float((unsigned)(v & 0xffffffffull));
}
__device__ __forceinline__ float hi32(unsigned long long v) {
    return __uint_as_float((unsigned)(v >> 32));
}
// cta-scope acquire (canonical pattern for async-proxy data landing in our own
// smem): avoids any cluster-scope fence cost (CCTL.IVALL) on every step.
__device__ __forceinline__ void mbar_wait(unsigned addr, unsigned ph) {
    unsigned done = 0;
    do {
        asm volatile("{\n\t.reg .pred p;\n\t"
            "mbarrier.try_wait.parity.acquire.cta.shared::cta.b64 p, [%1], %2, 0x989680;\n\t"
            "selp.b32 %0, 1, 0, p;\n\t}"
            : "=r"(done) : "r"(addr), "r"(ph) : "memory");
    } while (!done);
}

// ---------------------------------------------------------------------------
// Kernel 1: pre[d][t][n] = sum_k embed[sent[t']][k] * Wih_d[n][k] + bih[n] + bhh[n]
// ---------------------------------------------------------------------------
__global__ __launch_bounds__(256) void gemm_pre_kernel(
    const int* __restrict__ sent, const float* __restrict__ embed,
    const float* __restrict__ WihF, const float* __restrict__ bihF, const float* __restrict__ bhhF,
    const float* __restrict__ WihB, const float* __restrict__ bihB, const float* __restrict__ bhhB)
{
    const int d = blockIdx.z;
    const float* __restrict__ Wih = d ? WihB : WihF;
    const float* __restrict__ bih = d ? bihB : bihF;
    const float* __restrict__ bhh = d ? bhhB : bhhF;

    __shared__ __align__(16) float As[16][64];   // [k][m]
    __shared__ __align__(16) float Bs[16][64];   // [k][n]

    const int t0 = blockIdx.x * 64;
    const int n0 = blockIdx.y * 64;
    const int tid = threadIdx.x;
    const int tm = (tid & 15) * 4;
    const int tn = (tid >> 4) * 4;
    const int am = tid >> 2;         // 0..63
    const int ak = (tid & 3) * 4;    // 0,4,8,12

    const int tg = t0 + am;
    const int tp = d ? (L_ - 1 - tg) : tg;
    const float* arow = embed + (size_t)sent[tp] * E_;
    const float* brow = Wih + (size_t)(n0 + am) * E_;

    unsigned long long acc2[4][2];
    #pragma unroll
    for (int i = 0; i < 4; i++) { acc2[i][0] = 0ull; acc2[i][1] = 0ull; }

    for (int k0 = 0; k0 < E_; k0 += 16) {
        float4 av = *(const float4*)(arow + k0 + ak);
        float4 bv = *(const float4*)(brow + k0 + ak);
        __syncthreads();
        As[ak + 0][am] = av.x; As[ak + 1][am] = av.y;
        As[ak + 2][am] = av.z; As[ak + 3][am] = av.w;
        Bs[ak + 0][am] = bv.x; Bs[ak + 1][am] = bv.y;
        Bs[ak + 2][am] = bv.z; Bs[ak + 3][am] = bv.w;
        __syncthreads();
        #pragma unroll
        for (int kk = 0; kk < 16; kk++) {
            float a4[4];
            *(float4*)a4 = *(const float4*)&As[kk][tm];
            ulonglong2 b2 = *(const ulonglong2*)&Bs[kk][tn];
            #pragma unroll
            for (int i = 0; i < 4; i++) {
                unsigned long long asp;
                asm("mov.b64 %0, {%1, %1};" : "=l"(asp) : "f"(a4[i]));
                fma2(acc2[i][0], asp, b2.x);
                fma2(acc2[i][1], asp, b2.y);
            }
        }
    }
    #pragma unroll
    for (int i = 0; i < 4; i++) {
        float r[4] = { lo32(acc2[i][0]), hi32(acc2[i][0]),
                       lo32(acc2[i][1]), hi32(acc2[i][1]) };
        #pragma unroll
        for (int j = 0; j < 4; j++) {
            int n = n0 + tn + j;
            g_pre[d][t0 + tm + i][n] = r[j] + bih[n] + bhh[n];
        }
    }
}

// ---------------------------------------------------------------------------
// Kernel 2: LSTM recurrence, 8-CTA cluster per direction (round-7 structure,
// best measured). Warp w owns rows {q*256 + rank*32 + w*4 + i}; gates resolve
// in-warp via shfl; h broadcast = one predicated 16B st.async per lane<8 with
// mbarrier complete_tx (64 arrivals/dest/phase, expect_tx 1024 B).
// ---------------------------------------------------------------------------
__global__ void __cluster_dims__(8, 1, 1) __launch_bounds__(256, 1)
lstm_kernel(const float* __restrict__ WhhF, const float* __restrict__ WhhB,
            const float* __restrict__ h0, const float* __restrict__ c0)
{
    __shared__ __align__(16) float h_sm[2][H2_];
    __shared__ __align__(8) unsigned long long mbar[2];

    const int d = blockIdx.y;
    unsigned rank;
    asm("mov.u32 %0, %%cluster_ctarank;" : "=r"(rank));

    const int tid = threadIdx.x;
    const int w = tid >> 5;          // warp 0..7
    const int l = tid & 31;          // lane
    const int ri = l >> 1;           // row-in-warp 0..15
    const int half = l & 1;          // column half
    const int q = ri >> 2;           // gate: 0=i 1=f 2=g 3=o
    const int i4 = ri & 3;           // element within warp's 4 h-values
    const int grow = q * 256 + (int)rank * 32 + w * 4 + i4;   // global W row
    const float* __restrict__ Whh = d ? WhhB : WhhF;

    // Weights: 128 floats per thread = 64 packed f32x2 register pairs
    unsigned long long w2[64];
    {
        const float* wrow = Whh + (size_t)grow * H2_ + half * 128;
        #pragma unroll
        for (int i = 0; i < 32; i++) {
            ulonglong2 v = *(const ulonglong2*)(wrow + 4 * i);
            w2[2 * i] = v.x; w2[2 * i + 1] = v.y;
        }
    }

    const unsigned mb0 = (unsigned)__cvta_generic_to_shared(&mbar[0]);
    const unsigned mb1 = (unsigned)__cvta_generic_to_shared(&mbar[1]);
    if (tid == 0) {
        asm volatile("mbarrier.init.shared.b64 [%0], %1;" :: "r"(mb0), "r"(1) : "memory");
        asm volatile("mbarrier.init.shared.b64 [%0], %1;" :: "r"(mb1), "r"(1) : "memory");
        // pre-post phase 0 of both barriers (stores from steps 0 and 1)
        asm volatile("mbarrier.arrive.expect_tx.shared.b64 _, [%0], %1;" :: "r"(mb1), "r"(1024) : "memory");
        asm volatile("mbarrier.arrive.expect_tx.shared.b64 _, [%0], %1;" :: "r"(mb0), "r"(1024) : "memory");
    }
    h_sm[0][tid] = h0[d * H2_ + tid];
    const int hbase = (int)rank * 32 + w * 4;
    float cst = c0[d * H2_ + hbase + ((l >> 1) & 3)];
    __syncthreads();
    // barrier init + pre-posts must be cluster-visible before any peer st.async
    asm volatile("barrier.cluster.arrive.aligned;" ::: "memory");
    asm volatile("barrier.cluster.wait.aligned;"   ::: "memory");

    const float* __restrict__ pre = &g_pre[d][0][0];
    const unsigned hs0 = (unsigned)__cvta_generic_to_shared(&h_sm[0][hbase]);
    const unsigned hs1 = (unsigned)__cvta_generic_to_shared(&h_sm[1][hbase]);
    const float two_or_one = (q == 2) ? 2.f : 1.f;
    unsigned ph0 = 0, ph1 = 0;

    // hoisted per-lane remote addresses (dest CTA = l&7; store predicated l<8)
    const int dl = l & 7;
    unsigned ra0, ra1, rb0, rb1;
    asm("mapa.shared::cluster.u32 %0, %1, %2;" : "=r"(ra0) : "r"(hs0), "r"(dl));
    asm("mapa.shared::cluster.u32 %0, %1, %2;" : "=r"(ra1) : "r"(hs1), "r"(dl));
    asm("mapa.shared::cluster.u32 %0, %1, %2;" : "=r"(rb0) : "r"(mb0), "r"(dl));
    asm("mapa.shared::cluster.u32 %0, %1, %2;" : "=r"(rb1) : "r"(mb1), "r"(dl));

    for (int t = 0; t < L_; t++) {
        const int buf = t & 1;
        // prefetch input projection before blocking on the wait
        float p = __ldg(pre + (size_t)t * H4_ + grow);

        if (t > 0) {
            if (buf) { mbar_wait(mb1, ph1); ph1 ^= 1; }
            else     { mbar_wait(mb0, ph0); ph0 ^= 1; }
            // repost the barrier just consumed for its next use (step t+2)
            if (w == 0 && l == 0 && t <= L_ - 3) {
                const unsigned mbc = buf ? mb1 : mb0;
                asm volatile("mbarrier.arrive.expect_tx.shared.b64 _, [%0], %1;"
                             :: "r"(mbc), "r"(1024) : "memory");
            }
        }

        const float* hb = h_sm[buf] + half * 128;
        unsigned long long a0 = 0, a1 = 0, a2 = 0, a3 = 0;
        #pragma unroll
        for (int i = 0; i < 16; i++) {
            ulonglong2 hv0 = *(const ulonglong2*)(hb + 8 * i);
            ulonglong2 hv1 = *(const ulonglong2*)(hb + 8 * i + 4);
            fma2(a0, w2[4 * i + 0], hv0.x);
            fma2(a1, w2[4 * i + 1], hv0.y);
            fma2(a2, w2[4 * i + 2], hv1.x);
            fma2(a3, w2[4 * i + 3], hv1.y);
        }
        float s = (lo32(a0) + hi32(a0)) + (lo32(a1) + hi32(a1))
                + (lo32(a2) + hi32(a2)) + (lo32(a3) + hi32(a3));
        s += __shfl_xor_sync(0xffffffffu, s, 1);   // combine halves
        float z = s + p;

        // unified activation: sigmoid for i/f/o, tanh (=2*sig(2z)-1) for g
        float arg = z * two_or_one;
        float sig = 1.f / (1.f + __expf(-arg));
        float act = (q == 2) ? (2.f * sig - 1.f) : sig;

        // gather gate quadruple to the q=0 lanes (l in 0..7)
        float fA = __shfl_sync(0xffffffffu, act, (l + 8) & 31);
        float gA = __shfl_sync(0xffffffffu, act, (l + 16) & 31);
        float oA = __shfl_sync(0xffffffffu, act, (l + 24) & 31);
        cst = fA * cst + act * gA;
        float th = 2.f / (1.f + __expf(-2.f * cst)) - 1.f;
        float h = oA * th;

        // broadcast the warp's 4 h-values to all lanes
        float h0v = __shfl_sync(0xffffffffu, h, 0);
        float h1v = __shfl_sync(0xffffffffu, h, 2);
        float h2v = __shfl_sync(0xffffffffu, h, 4);
        float h3v = __shfl_sync(0xffffffffu, h, 6);

        if (t < L_ - 1) {
            // one predicated 16B st.async per lane<8 (no divergent branch)
            const unsigned ra = buf ? ra0 : ra1;   // next buffer
            const unsigned rb = buf ? rb0 : rb1;
            asm volatile("{\n\t.reg .pred p;\n\t"
                "setp.lt.s32 p, %5, 8;\n\t"
                "@p st.async.shared::cluster.mbarrier::complete_tx::bytes.v4.b32 "
                "[%0], {%1,%2,%3,%4}, [%6];\n\t}"
                :: "r"(ra), "f"(h0v), "f"(h1v), "f"(h2v), "f"(h3v),
                   "r"(l), "r"(rb) : "memory");
        }
        if (l == 0) {
            const int pos = d ? (L_ - 1 - t) : t;
            *(float4*)&g_h[d][pos][hbase] = make_float4(h0v, h1v, h2v, h3v);
        }
    }
    // all phases fully consumed by the final waits; plain exit sync
    asm volatile("barrier.cluster.arrive.aligned;" ::: "memory");
    asm volatile("barrier.cluster.wait.aligned;"   ::: "memory");
}

// ---------------------------------------------------------------------------
// Kernel 3: feats[p][tag] = concat(hf[p],hb[p]) . W_out[tag] + b_out[tag]
// ---------------------------------------------------------------------------
__global__ __launch_bounds__(256) void feats_kernel(
    const float* __restrict__ Wout, const float* __restrict__ bout)
{
    const int warp = threadIdx.x >> 5, lane = threadIdx.x & 31;
    const int p = blockIdx.x * 8 + warp;
    float x[16];
    #pragma unroll
    for (int i = 0; i < 8; i++) x[i] = g_h[0][p][lane + 32 * i];
    #pragma unroll
    for (int i = 0; i < 8; i++) x[8 + i] = g_h[1][p][lane + 32 * i];
    #pragma unroll
    for (int tag = 0; tag < T_; tag++) {
        const float* wrow = Wout + tag * (2 * H2_);
        float acc = 0.f;
        #pragma unroll
        for (int i = 0; i < 16; i++)
            acc += x[i] * wrow[(i < 8 ? 0 : 256) + lane + 32 * (i & 7)];
        #pragma unroll
        for (int o = 16; o > 0; o >>= 1) acc += __shfl_xor_sync(0xffffffffu, acc, o);
        if (lane == 0) g_feats[p][tag] = acc + bout[tag];
    }
}

// ---------------------------------------------------------------------------
// Kernel 4a: CRF chunk matrices (log-semiring parallel scan, 128 chunks x 16).
// ---------------------------------------------------------------------------
__global__ __launch_bounds__(256) void crf_chunks_kernel(
    const float* __restrict__ trans)
{
    const int warp = threadIdx.x >> 5, lane = threadIdx.x & 31;
    const int wc = blockIdx.x * 8 + warp;     // chunk id 0..127
    const int ln = (lane < T_) ? lane : 0;    // this lane's "next" state n

    float trr[T_];
    #pragma unroll
    for (int k = 0; k < T_; k++) trr[k] = trans[ln * T_ + k];

    float m[T_];
    #pragma unroll
    for (int p = 0; p < T_; p++) m[p] = (ln == p) ? 0.f : NEGI_;

    const float* ff = &g_feats[wc * CLEN_][0];
    for (int s = 0; s < CLEN_; s++) {
        const float emit = ff[s * T_ + ln];
        #pragma unroll
        for (int p = 0; p < T_; p++) {
            float v0 = __shfl_sync(0xffffffffu, m[p], 0) + trr[0];
            float v1 = __shfl_sync(0xffffffffu, m[p], 1) + trr[1];
            float v2 = __shfl_sync(0xffffffffu, m[p], 2) + trr[2];
            float v3 = __shfl_sync(0xffffffffu, m[p], 3) + trr[3];
            float v4 = __shfl_sync(0xffffffffu, m[p], 4) + trr[4];
            float v5 = __shfl_sync(0xffffffffu, m[p], 5) + trr[5];
            float mx = fmaxf(fmaxf(fmaxf(v0, v1), fmaxf(v2, v3)), fmaxf(v4, v5));
            float sum = __expf(v0 - mx) + __expf(v1 - mx) + __expf(v2 - mx)
                      + __expf(v3 - mx) + __expf(v4 - mx) + __expf(v5 - mx);
            m[p] = mx + __logf(sum) + emit;
        }
    }
    if (lane < T_) {
        #pragma unroll
        for (int p = 0; p < T_; p++) g_mats[wc][lane * T_ + p] = m[p];
    }
}

// ---------------------------------------------------------------------------
// Kernel 4b: gold score + fold chunk matrices into fv, final logsumexp.
// ---------------------------------------------------------------------------
__global__ __launch_bounds__(256) void crf_final_kernel(
    const int* __restrict__ tags, const float* __restrict__ trans,
    float* __restrict__ out)
{
    __shared__ float red[256];
    const int tid = threadIdx.x;

    // gold score
    float g = 0.f;
    for (int i = tid; i < L_; i += 256) {
        int cur = tags[i];
        int prev = (i == 0) ? START_ : tags[i - 1];
        g += trans[cur * T_ + prev] + g_feats[i][cur];
    }
    if (tid == 0) g += trans[STOP_ * T_ + tags[L_ - 1]];
    red[tid] = g;
    __syncthreads();
    for (int s = 128; s > 0; s >>= 1) {
        if (tid < s) red[tid] += red[tid + s];
        __syncthreads();
    }

    if (tid < 32) {
        const int ln = (tid < T_) ? tid : 0;
        float fv = (ln == START_) ? 0.f : NEG_;
        for (int c = 0; c < NCHUNK_; c++) {
            float r0 = g_mats[c][ln * T_ + 0], r1 = g_mats[c][ln * T_ + 1];
            float r2 = g_mats[c][ln * T_ + 2], r3 = g_mats[c][ln * T_ + 3];
            float r4 = g_mats[c][ln * T_ + 4], r5 = g_mats[c][ln * T_ + 5];
            float v0 = r0 + __shfl_sync(0xffffffffu, fv, 0);
            float v1 = r1 + __shfl_sync(0xffffffffu, fv, 1);
            float v2 = r2 + __shfl_sync(0xffffffffu, fv, 2);
            float v3 = r3 + __shfl_sync(0xffffffffu, fv, 3);
            float v4 = r4 + __shfl_sync(0xffffffffu, fv, 4);
            float v5 = r5 + __shfl_sync(0xffffffffu, fv, 5);
            float mx = fmaxf(fmaxf(fmaxf(v0, v1), fmaxf(v2, v3)), fmaxf(v4, v5));
            float sum = __expf(v0 - mx) + __expf(v1 - mx) + __expf(v2 - mx)
                      + __expf(v3 - mx) + __expf(v4 - mx) + __expf(v5 - mx);
            fv = mx + __logf(sum);
        }
        // final: logsumexp(fv + trans[STOP])
        float v = fv + trans[STOP_ * T_ + ln];
        if (tid >= T_) v = NEGI_;
        float mx = v;
        #pragma unroll
        for (int o = 4; o > 0; o >>= 1) mx = fmaxf(mx, __shfl_xor_sync(0xffu, mx, o));
        mx = __shfl_sync(0xffffffffu, mx, 0);
        float e = (tid < T_) ? __expf(v - mx) : 0.f;
        #pragma unroll
        for (int o = 4; o > 0; o >>= 1) e += __shfl_xor_sync(0xffu, e, o);
        if (tid == 0) out[0] = mx + __logf(e) - red[0];
    }
}

// ---------------------------------------------------------------------------
extern "C" void kernel_launch(void* const* d_in, const int* in_sizes, int n_in,
                              void* d_out, int out_size)
{
    const int*   sentence = (const int*)d_in[0];
    const int*   tags     = (const int*)d_in[1];
    const float* embed    = (const float*)d_in[2];
    const float* Wih_f    = (const float*)d_in[3];
    const float* Whh_f    = (const float*)d_in[4];
    const float* bih_f    = (const float*)d_in[5];
    const float* bhh_f    = (const float*)d_in[6];
    const float* Wih_b    = (const float*)d_in[7];
    const float* Whh_b    = (const float*)d_in[8];
    const float* bih_b    = (const float*)d_in[9];
    const float* bhh_b    = (const float*)d_in[10];
    const float* h0       = (const float*)d_in[11];
    const float* c0       = (const float*)d_in[12];
    const float* W_out    = (const float*)d_in[13];
    const float* b_out    = (const float*)d_in[14];
    const float* trans    = (const float*)d_in[15];
    float* out = (float*)d_out;

    gemm_pre_kernel<<<dim3(L_ / 64, H4_ / 64, 2), 256>>>(
        sentence, embed, Wih_f, bih_f, bhh_f, Wih_b, bih_b, bhh_b);
    lstm_kernel<<<dim3(8, 2), 256>>>(Whh_f, Whh_b, h0, c0);
    feats_kernel<<<L_ / 8, 256>>>(W_out, b_out);
    crf_chunks_kernel<<<NCHUNK_ / 8, 256>>>(trans);
    crf_final_kernel<<<1, 256>>>(tags, trans, out);
}

// round 12
// speedup vs baseline: 1.3751x; 1.1184x over previous
#include <cuda_runtime.h>

#define L_ 2048
#define E_ 256
#define H2_ 256
#define H4_ 1024
#define T_ 6
#define START_ 4
#define STOP_ 5
#define NEG_ (-10000.0f)
#define NEGI_ (-1.0e30f)
#define NCHUNK_ 128
#define CLEN_ (L_ / NCHUNK_)   // 16

// Scratch (static __device__ arrays: allocation-free per harness rules)
__device__ float g_pre[2][L_][H4_];    // 16 MB: input projections per direction
__device__ float g_h[2][L_][H2_];      // 4 MB: hidden states (position-indexed)
__device__ float g_feats[L_][T_];      // 48 KB: emission scores
__device__ float g_mats[NCHUNK_][40];  // CRF chunk matrices (6x6, padded)

__device__ __forceinline__ void fma2(unsigned long long& d,
                                     unsigned long long a, unsigned long long b) {
    asm("fma.rn.f32x2 %0, %1, %2, %0;" : "+l"(d) : "l"(a), "l"(b));
}
__device__ __forceinline__ float lo32(unsigned long long v) {
    return __uint_as_float((unsigned)(v & 0xffffffffull));
}
__device__ __forceinline__ float hi32(unsigned long long v) {
    return __uint_as_float((unsigned)(v >> 32));
}
__device__ __forceinline__ float tanh_ap(float x) {
    float r; asm("tanh.approx.f32 %0, %1;" : "=f"(r) : "f"(x)); return r;
}
// cta-scope acquire (sufficient: async-proxy data lands in our own smem and
// completion is signaled on our local mbarrier).
__device__ __forceinline__ void mbar_wait(unsigned addr, unsigned ph) {
    unsigned done = 0;
    do {
        asm volatile("{\n\t.reg .pred p;\n\t"
            "mbarrier.try_wait.parity.acquire.cta.shared::cta.b64 p, [%1], %2, 0x989680;\n\t"
            "selp.b32 %0, 1, 0, p;\n\t}"
            : "=r"(done) : "r"(addr), "r"(ph) : "memory");
    } while (!done);
}

// ---------------------------------------------------------------------------
// Kernel 1: pre[d][t][n] = sum_k embed[sent[t']][k] * Wih_d[n][k] + bih[n] + bhh[n]
// ---------------------------------------------------------------------------
__global__ __launch_bounds__(256) void gemm_pre_kernel(
    const int* __restrict__ sent, const float* __restrict__ embed,
    const float* __restrict__ WihF, const float* __restrict__ bihF, const float* __restrict__ bhhF,
    const float* __restrict__ WihB, const float* __restrict__ bihB, const float* __restrict__ bhhB)
{
    const int d = blockIdx.z;
    const float* __restrict__ Wih = d ? WihB : WihF;
    const float* __restrict__ bih = d ? bihB : bihF;
    const float* __restrict__ bhh = d ? bhhB : bhhF;

    __shared__ __align__(16) float As[16][64];   // [k][m]
    __shared__ __align__(16) float Bs[16][64];   // [k][n]

    const int t0 = blockIdx.x * 64;
    const int n0 = blockIdx.y * 64;
    const int tid = threadIdx.x;
    const int tm = (tid & 15) * 4;
    const int tn = (tid >> 4) * 4;
    const int am = tid >> 2;         // 0..63
    const int ak = (tid & 3) * 4;    // 0,4,8,12

    const int tg = t0 + am;
    const int tp = d ? (L_ - 1 - tg) : tg;
    const float* arow = embed + (size_t)sent[tp] * E_;
    const float* brow = Wih + (size_t)(n0 + am) * E_;

    unsigned long long acc2[4][2];
    #pragma unroll
    for (int i = 0; i < 4; i++) { acc2[i][0] = 0ull; acc2[i][1] = 0ull; }

    for (int k0 = 0; k0 < E_; k0 += 16) {
        float4 av = *(const float4*)(arow + k0 + ak);
        float4 bv = *(const float4*)(brow + k0 + ak);
        __syncthreads();
        As[ak + 0][am] = av.x; As[ak + 1][am] = av.y;
        As[ak + 2][am] = av.z; As[ak + 3][am] = av.w;
        Bs[ak + 0][am] = bv.x; Bs[ak + 1][am] = bv.y;
        Bs[ak + 2][am] = bv.z; Bs[ak + 3][am] = bv.w;
        __syncthreads();
        #pragma unroll
        for (int kk = 0; kk < 16; kk++) {
            float a4[4];
            *(float4*)a4 = *(const float4*)&As[kk][tm];
            ulonglong2 b2 = *(const ulonglong2*)&Bs[kk][tn];
            #pragma unroll
            for (int i = 0; i < 4; i++) {
                unsigned long long asp;
                asm("mov.b64 %0, {%1, %1};" : "=l"(asp) : "f"(a4[i]));
                fma2(acc2[i][0], asp, b2.x);
                fma2(acc2[i][1], asp, b2.y);
            }
        }
    }
    #pragma unroll
    for (int i = 0; i < 4; i++) {
        float r[4] = { lo32(acc2[i][0]), hi32(acc2[i][0]),
                       lo32(acc2[i][1]), hi32(acc2[i][1]) };
        #pragma unroll
        for (int j = 0; j < 4; j++) {
            int n = n0 + tn + j;
            g_pre[d][t0 + tm + i][n] = r[j] + bih[n] + bhh[n];
        }
    }
}

// ---------------------------------------------------------------------------
// Kernel 2: LSTM recurrence, 8-CTA cluster per direction (round-7 structure,
// best measured). CHANGE this round: all activations via tanh.approx MUFU.
//   sigmoid(x) = 0.5 + 0.5*tanh(0.5x);  tanh via tanh.approx directly.
// Cuts the two dependent exp/rcp chains (~44 cyc each) in the serial tail to
// ~20-24 cyc each.
// ---------------------------------------------------------------------------
__global__ void __cluster_dims__(8, 1, 1) __launch_bounds__(256, 1)
lstm_kernel(const float* __restrict__ WhhF, const float* __restrict__ WhhB,
            const float* __restrict__ h0, const float* __restrict__ c0)
{
    __shared__ __align__(16) float h_sm[2][H2_];
    __shared__ __align__(8) unsigned long long mbar[2];

    const int d = blockIdx.y;
    unsigned rank;
    asm("mov.u32 %0, %%cluster_ctarank;" : "=r"(rank));

    const int tid = threadIdx.x;
    const int w = tid >> 5;          // warp 0..7
    const int l = tid & 31;          // lane
    const int ri = l >> 1;           // row-in-warp 0..15
    const int half = l & 1;          // column half
    const int q = ri >> 2;           // gate: 0=i 1=f 2=g 3=o
    const int i4 = ri & 3;           // element within warp's 4 h-values
    const int grow = q * 256 + (int)rank * 32 + w * 4 + i4;   // global W row
    const float* __restrict__ Whh = d ? WhhB : WhhF;

    // Weights: 128 floats per thread = 64 packed f32x2 register pairs
    unsigned long long w2[64];
    {
        const float* wrow = Whh + (size_t)grow * H2_ + half * 128;
        #pragma unroll
        for (int i = 0; i < 32; i++) {
            ulonglong2 v = *(const ulonglong2*)(wrow + 4 * i);
            w2[2 * i] = v.x; w2[2 * i + 1] = v.y;
        }
    }

    const unsigned mb0 = (unsigned)__cvta_generic_to_shared(&mbar[0]);
    const unsigned mb1 = (unsigned)__cvta_generic_to_shared(&mbar[1]);
    if (tid == 0) {
        asm volatile("mbarrier.init.shared.b64 [%0], %1;" :: "r"(mb0), "r"(1) : "memory");
        asm volatile("mbarrier.init.shared.b64 [%0], %1;" :: "r"(mb1), "r"(1) : "memory");
        // pre-post phase 0 of both barriers (stores from steps 0 and 1)
        asm volatile("mbarrier.arrive.expect_tx.shared.b64 _, [%0], %1;" :: "r"(mb1), "r"(1024) : "memory");
        asm volatile("mbarrier.arrive.expect_tx.shared.b64 _, [%0], %1;" :: "r"(mb0), "r"(1024) : "memory");
    }
    h_sm[0][tid] = h0[d * H2_ + tid];
    const int hbase = (int)rank * 32 + w * 4;
    float cst = c0[d * H2_ + hbase + ((l >> 1) & 3)];
    __syncthreads();
    // barrier init + pre-posts must be cluster-visible before any peer st.async
    asm volatile("barrier.cluster.arrive.aligned;" ::: "memory");
    asm volatile("barrier.cluster.wait.aligned;"   ::: "memory");

    const float* __restrict__ pre = &g_pre[d][0][0];
    const unsigned hs0 = (unsigned)__cvta_generic_to_shared(&h_sm[0][hbase]);
    const unsigned hs1 = (unsigned)__cvta_generic_to_shared(&h_sm[1][hbase]);
    // activation constants: g-gate (q==2) uses tanh(z); others 0.5+0.5*tanh(z/2)
    const float kmul = (q == 2) ? 1.f : 0.5f;
    const float kscale = (q == 2) ? 1.f : 0.5f;
    const float kaff = (q == 2) ? 0.f : 0.5f;
    unsigned ph0 = 0, ph1 = 0;

    // hoisted per-lane remote addresses (dest CTA = l&7; store predicated l<8)
    const int dl = l & 7;
    unsigned ra0, ra1, rb0, rb1;
    asm("mapa.shared::cluster.u32 %0, %1, %2;" : "=r"(ra0) : "r"(hs0), "r"(dl));
    asm("mapa.shared::cluster.u32 %0, %1, %2;" : "=r"(ra1) : "r"(hs1), "r"(dl));
    asm("mapa.shared::cluster.u32 %0, %1, %2;" : "=r"(rb0) : "r"(mb0), "r"(dl));
    asm("mapa.shared::cluster.u32 %0, %1, %2;" : "=r"(rb1) : "r"(mb1), "r"(dl));

    for (int t = 0; t < L_; t++) {
        const int buf = t & 1;
        // prefetch input projection before blocking on the wait
        float p = __ldg(pre + (size_t)t * H4_ + grow);

        if (t > 0) {
            if (buf) { mbar_wait(mb1, ph1); ph1 ^= 1; }
            else     { mbar_wait(mb0, ph0); ph0 ^= 1; }
            // repost the barrier just consumed for its next use (step t+2)
            if (w == 0 && l == 0 && t <= L_ - 3) {
                const unsigned mbc = buf ? mb1 : mb0;
                asm volatile("mbarrier.arrive.expect_tx.shared.b64 _, [%0], %1;"
                             :: "r"(mbc), "r"(1024) : "memory");
            }
        }

        const float* hb = h_sm[buf] + half * 128;
        unsigned long long a0 = 0, a1 = 0, a2 = 0, a3 = 0;
        #pragma unroll
        for (int i = 0; i < 16; i++) {
            ulonglong2 hv0 = *(const ulonglong2*)(hb + 8 * i);
            ulonglong2 hv1 = *(const ulonglong2*)(hb + 8 * i + 4);
            fma2(a0, w2[4 * i + 0], hv0.x);
            fma2(a1, w2[4 * i + 1], hv0.y);
            fma2(a2, w2[4 * i + 2], hv1.x);
            fma2(a3, w2[4 * i + 3], hv1.y);
        }
        float s = (lo32(a0) + hi32(a0)) + (lo32(a1) + hi32(a1))
                + (lo32(a2) + hi32(a2)) + (lo32(a3) + hi32(a3));
        s += __shfl_xor_sync(0xffffffffu, s, 1);   // combine halves
        float z = s + p;

        // unified MUFU activation: tanh for g, sigmoid via tanh identity
        float tt = tanh_ap(z * kmul);
        float act = fmaf(kscale, tt, kaff);

        // gather gate quadruple to the q=0 lanes (l in 0..7)
        float fA = __shfl_sync(0xffffffffu, act, (l + 8) & 31);
        float gA = __shfl_sync(0xffffffffu, act, (l + 16) & 31);
        float oA = __shfl_sync(0xffffffffu, act, (l + 24) & 31);
        cst = fA * cst + act * gA;
        float th = tanh_ap(cst);
        float h = oA * th;

        // broadcast the warp's 4 h-values to all lanes
        float h0v = __shfl_sync(0xffffffffu, h, 0);
        float h1v = __shfl_sync(0xffffffffu, h, 2);
        float h2v = __shfl_sync(0xffffffffu, h, 4);
        float h3v = __shfl_sync(0xffffffffu, h, 6);

        if (t < L_ - 1) {
            // one predicated 16B st.async per lane<8 (no divergent branch)
            const unsigned ra = buf ? ra0 : ra1;   // next buffer
            const unsigned rb = buf ? rb0 : rb1;
            asm volatile("{\n\t.reg .pred p;\n\t"
                "setp.lt.s32 p, %5, 8;\n\t"
                "@p st.async.shared::cluster.mbarrier::complete_tx::bytes.v4.b32 "
                "[%0], {%1,%2,%3,%4}, [%6];\n\t}"
                :: "r"(ra), "f"(h0v), "f"(h1v), "f"(h2v), "f"(h3v),
                   "r"(l), "r"(rb) : "memory");
        }
        if (l == 0) {
            const int pos = d ? (L_ - 1 - t) : t;
            *(float4*)&g_h[d][pos][hbase] = make_float4(h0v, h1v, h2v, h3v);
        }
    }
    // all phases fully consumed by the final waits; plain exit sync
    asm volatile("barrier.cluster.arrive.aligned;" ::: "memory");
    asm volatile("barrier.cluster.wait.aligned;"   ::: "memory");
}

// ---------------------------------------------------------------------------
// Kernel 3: feats[p][tag] = concat(hf[p],hb[p]) . W_out[tag] + b_out[tag]
// ---------------------------------------------------------------------------
__global__ __launch_bounds__(256) void feats_kernel(
    const float* __restrict__ Wout, const float* __restrict__ bout)
{
    const int warp = threadIdx.x >> 5, lane = threadIdx.x & 31;
    const int p = blockIdx.x * 8 + warp;
    float x[16];
    #pragma unroll
    for (int i = 0; i < 8; i++) x[i] = g_h[0][p][lane + 32 * i];
    #pragma unroll
    for (int i = 0; i < 8; i++) x[8 + i] = g_h[1][p][lane + 32 * i];
    #pragma unroll
    for (int tag = 0; tag < T_; tag++) {
        const float* wrow = Wout + tag * (2 * H2_);
        float acc = 0.f;
        #pragma unroll
        for (int i = 0; i < 16; i++)
            acc += x[i] * wrow[(i < 8 ? 0 : 256) + lane + 32 * (i & 7)];
        #pragma unroll
        for (int o = 16; o > 0; o >>= 1) acc += __shfl_xor_sync(0xffffffffu, acc, o);
        if (lane == 0) g_feats[p][tag] = acc + bout[tag];
    }
}

// ---------------------------------------------------------------------------
// Kernel 4a: CRF chunk matrices (log-semiring parallel scan, 128 chunks x 16).
// ---------------------------------------------------------------------------
__global__ __launch_bounds__(256) void crf_chunks_kernel(
    const float* __restrict__ trans)
{
    const int warp = threadIdx.x >> 5, lane = threadIdx.x & 31;
    const int wc = blockIdx.x * 8 + warp;     // chunk id 0..127
    const int ln = (lane < T_) ? lane : 0;    // this lane's "next" state n

    float trr[T_];
    #pragma unroll
    for (int k = 0; k < T_; k++) trr[k] = trans[ln * T_ + k];

    float m[T_];
    #pragma unroll
    for (int p = 0; p < T_; p++) m[p] = (ln == p) ? 0.f : NEGI_;

    const float* ff = &g_feats[wc * CLEN_][0];
    for (int s = 0; s < CLEN_; s++) {
        const float emit = ff[s * T_ + ln];
        #pragma unroll
        for (int p = 0; p < T_; p++) {
            float v0 = __shfl_sync(0xffffffffu, m[p], 0) + trr[0];
            float v1 = __shfl_sync(0xffffffffu, m[p], 1) + trr[1];
            float v2 = __shfl_sync(0xffffffffu, m[p], 2) + trr[2];
            float v3 = __shfl_sync(0xffffffffu, m[p], 3) + trr[3];
            float v4 = __shfl_sync(0xffffffffu, m[p], 4) + trr[4];
            float v5 = __shfl_sync(0xffffffffu, m[p], 5) + trr[5];
            float mx = fmaxf(fmaxf(fmaxf(v0, v1), fmaxf(v2, v3)), fmaxf(v4, v5));
            float sum = __expf(v0 - mx) + __expf(v1 - mx) + __expf(v2 - mx)
                      + __expf(v3 - mx) + __expf(v4 - mx) + __expf(v5 - mx);
            m[p] = mx + __logf(sum) + emit;
        }
    }
    if (lane < T_) {
        #pragma unroll
        for (int p = 0; p < T_; p++) g_mats[wc][lane * T_ + p] = m[p];
    }
}

// ---------------------------------------------------------------------------
// Kernel 4b: gold score + fold chunk matrices into fv, final logsumexp.
// ---------------------------------------------------------------------------
__global__ __launch_bounds__(256) void crf_final_kernel(
    const int* __restrict__ tags, const float* __restrict__ trans,
    float* __restrict__ out)
{
    __shared__ float red[256];
    const int tid = threadIdx.x;

    // gold score
    float g = 0.f;
    for (int i = tid; i < L_; i += 256) {
        int cur = tags[i];
        int prev = (i == 0) ? START_ : tags[i - 1];
        g += trans[cur * T_ + prev] + g_feats[i][cur];
    }
    if (tid == 0) g += trans[STOP_ * T_ + tags[L_ - 1]];
    red[tid] = g;
    __syncthreads();
    for (int s = 128; s > 0; s >>= 1) {
        if (tid < s) red[tid] += red[tid + s];
        __syncthreads();
    }

    if (tid < 32) {
        const int ln = (tid < T_) ? tid : 0;
        float fv = (ln == START_) ? 0.f : NEG_;
        for (int c = 0; c < NCHUNK_; c++) {
            float r0 = g_mats[c][ln * T_ + 0], r1 = g_mats[c][ln * T_ + 1];
            float r2 = g_mats[c][ln * T_ + 2], r3 = g_mats[c][ln * T_ + 3];
            float r4 = g_mats[c][ln * T_ + 4], r5 = g_mats[c][ln * T_ + 5];
            float v0 = r0 + __shfl_sync(0xffffffffu, fv, 0);
            float v1 = r1 + __shfl_sync(0xffffffffu, fv, 1);
            float v2 = r2 + __shfl_sync(0xffffffffu, fv, 2);
            float v3 = r3 + __shfl_sync(0xffffffffu, fv, 3);
            float v4 = r4 + __shfl_sync(0xffffffffu, fv, 4);
            float v5 = r5 + __shfl_sync(0xffffffffu, fv, 5);
            float mx = fmaxf(fmaxf(fmaxf(v0, v1), fmaxf(v2, v3)), fmaxf(v4, v5));
            float sum = __expf(v0 - mx) + __expf(v1 - mx) + __expf(v2 - mx)
                      + __expf(v3 - mx) + __expf(v4 - mx) + __expf(v5 - mx);
            fv = mx + __logf(sum);
        }
        // final: logsumexp(fv + trans[STOP])
        float v = fv + trans[STOP_ * T_ + ln];
        if (tid >= T_) v = NEGI_;
        float mx = v;
        #pragma unroll
        for (int o = 4; o > 0; o >>= 1) mx = fmaxf(mx, __shfl_xor_sync(0xffu, mx, o));
        mx = __shfl_sync(0xffffffffu, mx, 0);
        float e = (tid < T_) ? __expf(v - mx) : 0.f;
        #pragma unroll
        for (int o = 4; o > 0; o >>= 1) e += __shfl_xor_sync(0xffu, e, o);
        if (tid == 0) out[0] = mx + __logf(e) - red[0];
    }
}

// ---------------------------------------------------------------------------
extern "C" void kernel_launch(void* const* d_in, const int* in_sizes, int n_in,
                              void* d_out, int out_size)
{
    const int*   sentence = (const int*)d_in[0];
    const int*   tags     = (const int*)d_in[1];
    const float* embed    = (const float*)d_in[2];
    const float* Wih_f    = (const float*)d_in[3];
    const float* Whh_f    = (const float*)d_in[4];
    const float* bih_f    = (const float*)d_in[5];
    const float* bhh_f    = (const float*)d_in[6];
    const float* Wih_b    = (const float*)d_in[7];
    const float* Whh_b    = (const float*)d_in[8];
    const float* bih_b    = (const float*)d_in[9];
    const float* bhh_b    = (const float*)d_in[10];
    const float* h0       = (const float*)d_in[11];
    const float* c0       = (const float*)d_in[12];
    const float* W_out    = (const float*)d_in[13];
    const float* b_out    = (const float*)d_in[14];
    const float* trans    = (const float*)d_in[15];
    float* out = (float*)d_out;

    gemm_pre_kernel<<<dim3(L_ / 64, H4_ / 64, 2), 256>>>(
        sentence, embed, Wih_f, bih_f, bhh_f, Wih_b, bih_b, bhh_b);
    lstm_kernel<<<dim3(8, 2), 256>>>(Whh_f, Whh_b, h0, c0);
    feats_kernel<<<L_ / 8, 256>>>(W_out, b_out);
    crf_chunks_kernel<<<NCHUNK_ / 8, 256>>>(trans);
    crf_final_kernel<<<1, 256>>>(tags, trans, out);
}

// round 13
// speedup vs baseline: 1.4202x; 1.0327x over previous
#include <cuda_runtime.h>

#define L_ 2048
#define E_ 256
#define H2_ 256
#define H4_ 1024
#define T_ 6
#define START_ 4
#define STOP_ 5
#define NEG_ (-10000.0f)
#define NEGI_ (-1.0e30f)
#define NCHUNK_ 128
#define CLEN_ (L_ / NCHUNK_)   // 16

// Scratch (static __device__ arrays: allocation-free per harness rules)
__device__ float g_pre[2][L_][H4_];    // 16 MB: input projections per direction
__device__ float g_h[2][L_][H2_];      // 4 MB: hidden states (position-indexed)
__device__ float g_feats[L_][T_];      // 48 KB: emission scores
__device__ float g_mats[NCHUNK_][40];  // CRF chunk matrices (6x6, padded)

__device__ __forceinline__ void fma2(unsigned long long& d,
                                     unsigned long long a, unsigned long long b) {
    asm("fma.rn.f32x2 %0, %1, %2, %0;" : "+l"(d) : "l"(a), "l"(b));
}
__device__ __forceinline__ float lo32(unsigned long long v) {
    return __uint_as_float((unsigned)(v & 0xffffffffull));
}
__device__ __forceinline__ float hi32(unsigned long long v) {
    return __uint_as_float((unsigned)(v >> 32));
}
__device__ __forceinline__ float tanh_ap(float x) {
    float r; asm("tanh.approx.f32 %0, %1;" : "=f"(r) : "f"(x)); return r;
}
// cta-scope acquire (sufficient: async-proxy data lands in our own smem and
// completion is signaled on our local mbarrier).
__device__ __forceinline__ void mbar_wait(unsigned addr, unsigned ph) {
    unsigned done = 0;
    do {
        asm volatile("{\n\t.reg .pred p;\n\t"
            "mbarrier.try_wait.parity.acquire.cta.shared::cta.b64 p, [%1], %2, 0x989680;\n\t"
            "selp.b32 %0, 1, 0, p;\n\t}"
            : "=r"(done) : "r"(addr), "r"(ph) : "memory");
    } while (!done);
}

// ---------------------------------------------------------------------------
// Kernel 1: pre[d][t][n] = sum_k embed[sent[t']][k] * Wih_d[n][k] + bih[n] + bhh[n]
// ---------------------------------------------------------------------------
__global__ __launch_bounds__(256) void gemm_pre_kernel(
    const int* __restrict__ sent, const float* __restrict__ embed,
    const float* __restrict__ WihF, const float* __restrict__ bihF, const float* __restrict__ bhhF,
    const float* __restrict__ WihB, const float* __restrict__ bihB, const float* __restrict__ bhhB)
{
    const int d = blockIdx.z;
    const float* __restrict__ Wih = d ? WihB : WihF;
    const float* __restrict__ bih = d ? bihB : bihF;
    const float* __restrict__ bhh = d ? bhhB : bhhF;

    __shared__ __align__(16) float As[16][64];   // [k][m]
    __shared__ __align__(16) float Bs[16][64];   // [k][n]

    const int t0 = blockIdx.x * 64;
    const int n0 = blockIdx.y * 64;
    const int tid = threadIdx.x;
    const int tm = (tid & 15) * 4;
    const int tn = (tid >> 4) * 4;
    const int am = tid >> 2;         // 0..63
    const int ak = (tid & 3) * 4;    // 0,4,8,12

    const int tg = t0 + am;
    const int tp = d ? (L_ - 1 - tg) : tg;
    const float* arow = embed + (size_t)sent[tp] * E_;
    const float* brow = Wih + (size_t)(n0 + am) * E_;

    unsigned long long acc2[4][2];
    #pragma unroll
    for (int i = 0; i < 4; i++) { acc2[i][0] = 0ull; acc2[i][1] = 0ull; }

    for (int k0 = 0; k0 < E_; k0 += 16) {
        float4 av = *(const float4*)(arow + k0 + ak);
        float4 bv = *(const float4*)(brow + k0 + ak);
        __syncthreads();
        As[ak + 0][am] = av.x; As[ak + 1][am] = av.y;
        As[ak + 2][am] = av.z; As[ak + 3][am] = av.w;
        Bs[ak + 0][am] = bv.x; Bs[ak + 1][am] = bv.y;
        Bs[ak + 2][am] = bv.z; Bs[ak + 3][am] = bv.w;
        __syncthreads();
        #pragma unroll
        for (int kk = 0; kk < 16; kk++) {
            float a4[4];
            *(float4*)a4 = *(const float4*)&As[kk][tm];
            ulonglong2 b2 = *(const ulonglong2*)&Bs[kk][tn];
            #pragma unroll
            for (int i = 0; i < 4; i++) {
                unsigned long long asp;
                asm("mov.b64 %0, {%1, %1};" : "=l"(asp) : "f"(a4[i]));
                fma2(acc2[i][0], asp, b2.x);
                fma2(acc2[i][1], asp, b2.y);
            }
        }
    }
    #pragma unroll
    for (int i = 0; i < 4; i++) {
        float r[4] = { lo32(acc2[i][0]), hi32(acc2[i][0]),
                       lo32(acc2[i][1]), hi32(acc2[i][1]) };
        #pragma unroll
        for (int j = 0; j < 4; j++) {
            int n = n0 + tn + j;
            g_pre[d][t0 + tm + i][n] = r[j] + bih[n] + bhh[n];
        }
    }
}

// ---------------------------------------------------------------------------
// Kernel 2: LSTM recurrence, 8-CTA cluster per direction.
// CHANGE this round: all-lane h computation. The gate gather is remapped so
// lane l gathers the (i,f,g,o) acts of element e = l>>3 (sources q*8 + 2e,
// 4 parallel shfls) and maintains that element's c-state. Every lane then
// holds a valid h and ships it DIRECTLY as one 4-byte st.async to dest CTA
// l&7 ((element,dest) bijective over 32 lanes) -- the h-broadcast shfl round
// disappears from the critical path. 256 msgs x 4 B per dest per phase;
// expect_tx stays 1024 B.
// ---------------------------------------------------------------------------
__global__ void __cluster_dims__(8, 1, 1) __launch_bounds__(256, 1)
lstm_kernel(const float* __restrict__ WhhF, const float* __restrict__ WhhB,
            const float* __restrict__ h0, const float* __restrict__ c0)
{
    __shared__ __align__(16) float h_sm[2][H2_];
    __shared__ __align__(8) unsigned long long mbar[2];

    const int d = blockIdx.y;
    unsigned rank;
    asm("mov.u32 %0, %%cluster_ctarank;" : "=r"(rank));

    const int tid = threadIdx.x;
    const int w = tid >> 5;          // warp 0..7
    const int l = tid & 31;          // lane
    const int ri = l >> 1;           // row-in-warp 0..15
    const int half = l & 1;          // column half
    const int q = ri >> 2;           // own gate: 0=i 1=f 2=g 3=o (= l>>3)
    const int i4 = ri & 3;           // own element within warp's 4 h-values
    const int e = l >> 3;            // element this lane FINISHES (c/h owner)
    const int grow = q * 256 + (int)rank * 32 + w * 4 + i4;   // global W row
    const float* __restrict__ Whh = d ? WhhB : WhhF;

    // Weights: 128 floats per thread = 64 packed f32x2 register pairs
    unsigned long long w2[64];
    {
        const float* wrow = Whh + (size_t)grow * H2_ + half * 128;
        #pragma unroll
        for (int i = 0; i < 32; i++) {
            ulonglong2 v = *(const ulonglong2*)(wrow + 4 * i);
            w2[2 * i] = v.x; w2[2 * i + 1] = v.y;
        }
    }

    const unsigned mb0 = (unsigned)__cvta_generic_to_shared(&mbar[0]);
    const unsigned mb1 = (unsigned)__cvta_generic_to_shared(&mbar[1]);
    if (tid == 0) {
        asm volatile("mbarrier.init.shared.b64 [%0], %1;" :: "r"(mb0), "r"(1) : "memory");
        asm volatile("mbarrier.init.shared.b64 [%0], %1;" :: "r"(mb1), "r"(1) : "memory");
        // pre-post phase 0 of both barriers (stores from steps 0 and 1)
        asm volatile("mbarrier.arrive.expect_tx.shared.b64 _, [%0], %1;" :: "r"(mb1), "r"(1024) : "memory");
        asm volatile("mbarrier.arrive.expect_tx.shared.b64 _, [%0], %1;" :: "r"(mb0), "r"(1024) : "memory");
    }
    h_sm[0][tid] = h0[d * H2_ + tid];
    const int hbase = (int)rank * 32 + w * 4;
    float cst = c0[d * H2_ + hbase + e];     // c-state for element e (8x repl)
    __syncthreads();
    // barrier init + pre-posts must be cluster-visible before any peer st.async
    asm volatile("barrier.cluster.arrive.aligned;" ::: "memory");
    asm volatile("barrier.cluster.wait.aligned;"   ::: "memory");

    const float* __restrict__ pre = &g_pre[d][0][0];
    const unsigned hs0 = (unsigned)__cvta_generic_to_shared(&h_sm[0][hbase]);
    const unsigned hs1 = (unsigned)__cvta_generic_to_shared(&h_sm[1][hbase]);
    // activation constants: g-gate (q==2) uses tanh(z); others 0.5+0.5*tanh(z/2)
    const float kmul = (q == 2) ? 1.f : 0.5f;
    const float kscale = (q == 2) ? 1.f : 0.5f;
    const float kaff = (q == 2) ? 0.f : 0.5f;
    unsigned ph0 = 0, ph1 = 0;

    // gate-gather shfl sources for element e: lanes q'*8 + 2e
    const int srcI = 2 * e;
    // hoisted per-lane remote addresses: dest CTA = l&7, slot = element e
    const int dl = l & 7;
    unsigned ra0, ra1, rb0, rb1;
    asm("mapa.shared::cluster.u32 %0, %1, %2;" : "=r"(ra0) : "r"(hs0 + e * 4u), "r"(dl));
    asm("mapa.shared::cluster.u32 %0, %1, %2;" : "=r"(ra1) : "r"(hs1 + e * 4u), "r"(dl));
    asm("mapa.shared::cluster.u32 %0, %1, %2;" : "=r"(rb0) : "r"(mb0), "r"(dl));
    asm("mapa.shared::cluster.u32 %0, %1, %2;" : "=r"(rb1) : "r"(mb1), "r"(dl));

    for (int t = 0; t < L_; t++) {
        const int buf = t & 1;
        // prefetch input projection before blocking on the wait
        float p = __ldg(pre + (size_t)t * H4_ + grow);

        if (t > 0) {
            if (buf) { mbar_wait(mb1, ph1); ph1 ^= 1; }
            else     { mbar_wait(mb0, ph0); ph0 ^= 1; }
            // repost the barrier just consumed for its next use (step t+2);
            // must precede this CTA's own st.async in program order.
            if (w == 0 && l == 0 && t <= L_ - 3) {
                const unsigned mbc = buf ? mb1 : mb0;
                asm volatile("mbarrier.arrive.expect_tx.shared.b64 _, [%0], %1;"
                             :: "r"(mbc), "r"(1024) : "memory");
            }
        }

        const float* hb = h_sm[buf] + half * 128;
        unsigned long long a0 = 0, a1 = 0, a2 = 0, a3 = 0;
        #pragma unroll
        for (int i = 0; i < 16; i++) {
            ulonglong2 hv0 = *(const ulonglong2*)(hb + 8 * i);
            ulonglong2 hv1 = *(const ulonglong2*)(hb + 8 * i + 4);
            fma2(a0, w2[4 * i + 0], hv0.x);
            fma2(a1, w2[4 * i + 1], hv0.y);
            fma2(a2, w2[4 * i + 2], hv1.x);
            fma2(a3, w2[4 * i + 3], hv1.y);
        }
        float s = (lo32(a0) + hi32(a0)) + (lo32(a1) + hi32(a1))
                + (lo32(a2) + hi32(a2)) + (lo32(a3) + hi32(a3));
        s += __shfl_xor_sync(0xffffffffu, s, 1);   // combine halves
        float z = s + p;

        // unified MUFU activation: tanh for g, sigmoid via tanh identity
        float tt = tanh_ap(z * kmul);
        float act = fmaf(kscale, tt, kaff);

        // gather the full (i,f,g,o) quadruple of element e (4 parallel shfls)
        float iA = __shfl_sync(0xffffffffu, act, srcI);
        float fA = __shfl_sync(0xffffffffu, act, srcI + 8);
        float gA = __shfl_sync(0xffffffffu, act, srcI + 16);
        float oA = __shfl_sync(0xffffffffu, act, srcI + 24);
        cst = fA * cst + iA * gA;
        float th = tanh_ap(cst);
        float h = oA * th;    // valid in EVERY lane (element e)

        if (t < L_ - 1) {
            // every lane ships its element's h (4 B) to its dest CTA
            const unsigned ra = buf ? ra0 : ra1;   // next buffer
            const unsigned rb = buf ? rb0 : rb1;
            asm volatile("st.async.shared::cluster.mbarrier::complete_tx::bytes.b32 "
                         "[%0], %1, [%2];"
                         :: "r"(ra), "r"(__float_as_uint(h)), "r"(rb) : "memory");
        }
        if (dl == 0) {
            const int pos = d ? (L_ - 1 - t) : t;
            g_h[d][pos][hbase + e] = h;
        }
    }
    // all phases fully consumed by the final waits; plain exit sync
    asm volatile("barrier.cluster.arrive.aligned;" ::: "memory");
    asm volatile("barrier.cluster.wait.aligned;"   ::: "memory");
}

// ---------------------------------------------------------------------------
// Kernel 3: feats[p][tag] = concat(hf[p],hb[p]) . W_out[tag] + b_out[tag]
// ---------------------------------------------------------------------------
__global__ __launch_bounds__(256) void feats_kernel(
    const float* __restrict__ Wout, const float* __restrict__ bout)
{
    const int warp = threadIdx.x >> 5, lane = threadIdx.x & 31;
    const int p = blockIdx.x * 8 + warp;
    float x[16];
    #pragma unroll
    for (int i = 0; i < 8; i++) x[i] = g_h[0][p][lane + 32 * i];
    #pragma unroll
    for (int i = 0; i < 8; i++) x[8 + i] = g_h[1][p][lane + 32 * i];
    #pragma unroll
    for (int tag = 0; tag < T_; tag++) {
        const float* wrow = Wout + tag * (2 * H2_);
        float acc = 0.f;
        #pragma unroll
        for (int i = 0; i < 16; i++)
            acc += x[i] * wrow[(i < 8 ? 0 : 256) + lane + 32 * (i & 7)];
        #pragma unroll
        for (int o = 16; o > 0; o >>= 1) acc += __shfl_xor_sync(0xffffffffu, acc, o);
        if (lane == 0) g_feats[p][tag] = acc + bout[tag];
    }
}

// ---------------------------------------------------------------------------
// Kernel 4a: CRF chunk matrices (log-semiring parallel scan, 128 chunks x 16).
// ---------------------------------------------------------------------------
__global__ __launch_bounds__(256) void crf_chunks_kernel(
    const float* __restrict__ trans)
{
    const int warp = threadIdx.x >> 5, lane = threadIdx.x & 31;
    const int wc = blockIdx.x * 8 + warp;     // chunk id 0..127
    const int ln = (lane < T_) ? lane : 0;    // this lane's "next" state n

    float trr[T_];
    #pragma unroll
    for (int k = 0; k < T_; k++) trr[k] = trans[ln * T_ + k];

    float m[T_];
    #pragma unroll
    for (int p = 0; p < T_; p++) m[p] = (ln == p) ? 0.f : NEGI_;

    const float* ff = &g_feats[wc * CLEN_][0];
    for (int s = 0; s < CLEN_; s++) {
        const float emit = ff[s * T_ + ln];
        #pragma unroll
        for (int p = 0; p < T_; p++) {
            float v0 = __shfl_sync(0xffffffffu, m[p], 0) + trr[0];
            float v1 = __shfl_sync(0xffffffffu, m[p], 1) + trr[1];
            float v2 = __shfl_sync(0xffffffffu, m[p], 2) + trr[2];
            float v3 = __shfl_sync(0xffffffffu, m[p], 3) + trr[3];
            float v4 = __shfl_sync(0xffffffffu, m[p], 4) + trr[4];
            float v5 = __shfl_sync(0xffffffffu, m[p], 5) + trr[5];
            float mx = fmaxf(fmaxf(fmaxf(v0, v1), fmaxf(v2, v3)), fmaxf(v4, v5));
            float sum = __expf(v0 - mx) + __expf(v1 - mx) + __expf(v2 - mx)
                      + __expf(v3 - mx) + __expf(v4 - mx) + __expf(v5 - mx);
            m[p] = mx + __logf(sum) + emit;
        }
    }
    if (lane < T_) {
        #pragma unroll
        for (int p = 0; p < T_; p++) g_mats[wc][lane * T_ + p] = m[p];
    }
}

// ---------------------------------------------------------------------------
// Kernel 4b: gold score + fold chunk matrices into fv, final logsumexp.
// ---------------------------------------------------------------------------
__global__ __launch_bounds__(256) void crf_final_kernel(
    const int* __restrict__ tags, const float* __restrict__ trans,
    float* __restrict__ out)
{
    __shared__ float red[256];
    const int tid = threadIdx.x;

    // gold score
    float g = 0.f;
    for (int i = tid; i < L_; i += 256) {
        int cur = tags[i];
        int prev = (i == 0) ? START_ : tags[i - 1];
        g += trans[cur * T_ + prev] + g_feats[i][cur];
    }
    if (tid == 0) g += trans[STOP_ * T_ + tags[L_ - 1]];
    red[tid] = g;
    __syncthreads();
    for (int s = 128; s > 0; s >>= 1) {
        if (tid < s) red[tid] += red[tid + s];
        __syncthreads();
    }

    if (tid < 32) {
        const int ln = (tid < T_) ? tid : 0;
        float fv = (ln == START_) ? 0.f : NEG_;
        for (int c = 0; c < NCHUNK_; c++) {
            float r0 = g_mats[c][ln * T_ + 0], r1 = g_mats[c][ln * T_ + 1];
            float r2 = g_mats[c][ln * T_ + 2], r3 = g_mats[c][ln * T_ + 3];
            float r4 = g_mats[c][ln * T_ + 4], r5 = g_mats[c][ln * T_ + 5];
            float v0 = r0 + __shfl_sync(0xffffffffu, fv, 0);
            float v1 = r1 + __shfl_sync(0xffffffffu, fv, 1);
            float v2 = r2 + __shfl_sync(0xffffffffu, fv, 2);
            float v3 = r3 + __shfl_sync(0xffffffffu, fv, 3);
            float v4 = r4 + __shfl_sync(0xffffffffu, fv, 4);
            float v5 = r5 + __shfl_sync(0xffffffffu, fv, 5);
            float mx = fmaxf(fmaxf(fmaxf(v0, v1), fmaxf(v2, v3)), fmaxf(v4, v5));
            float sum = __expf(v0 - mx) + __expf(v1 - mx) + __expf(v2 - mx)
                      + __expf(v3 - mx) + __expf(v4 - mx) + __expf(v5 - mx);
            fv = mx + __logf(sum);
        }
        // final: logsumexp(fv + trans[STOP])
        float v = fv + trans[STOP_ * T_ + ln];
        if (tid >= T_) v = NEGI_;
        float mx = v;
        #pragma unroll
        for (int o = 4; o > 0; o >>= 1) mx = fmaxf(mx, __shfl_xor_sync(0xffu, mx, o));
        mx = __shfl_sync(0xffffffffu, mx, 0);
        float e = (tid < T_) ? __expf(v - mx) : 0.f;
        #pragma unroll
        for (int o = 4; o > 0; o >>= 1) e += __shfl_xor_sync(0xffu, e, o);
        if (tid == 0) out[0] = mx + __logf(e) - red[0];
    }
}

// ---------------------------------------------------------------------------
extern "C" void kernel_launch(void* const* d_in, const int* in_sizes, int n_in,
                              void* d_out, int out_size)
{
    const int*   sentence = (const int*)d_in[0];
    const int*   tags     = (const int*)d_in[1];
    const float* embed    = (const float*)d_in[2];
    const float* Wih_f    = (const float*)d_in[3];
    const float* Whh_f    = (const float*)d_in[4];
    const float* bih_f    = (const float*)d_in[5];
    const float* bhh_f    = (const float*)d_in[6];
    const float* Wih_b    = (const float*)d_in[7];
    const float* Whh_b    = (const float*)d_in[8];
    const float* bih_b    = (const float*)d_in[9];
    const float* bhh_b    = (const float*)d_in[10];
    const float* h0       = (const float*)d_in[11];
    const float* c0       = (const float*)d_in[12];
    const float* W_out    = (const float*)d_in[13];
    const float* b_out    = (const float*)d_in[14];
    const float* trans    = (const float*)d_in[15];
    float* out = (float*)d_out;

    gemm_pre_kernel<<<dim3(L_ / 64, H4_ / 64, 2), 256>>>(
        sentence, embed, Wih_f, bih_f, bhh_f, Wih_b, bih_b, bhh_b);
    lstm_kernel<<<dim3(8, 2), 256>>>(Whh_f, Whh_b, h0, c0);
    feats_kernel<<<L_ / 8, 256>>>(W_out, b_out);
    crf_chunks_kernel<<<NCHUNK_ / 8, 256>>>(trans);
    crf_final_kernel<<<1, 256>>>(tags, trans, out);
}

// round 14
// speedup vs baseline: 1.4743x; 1.0381x over previous
#include <cuda_runtime.h>

#define L_ 2048
#define E_ 256
#define H2_ 256
#define H4_ 1024
#define T_ 6
#define START_ 4
#define STOP_ 5
#define NEG_ (-10000.0f)
#define NEGI_ (-1.0e30f)
#define NCHUNK_ 128
#define CLEN_ (L_ / NCHUNK_)   // 16

// Scratch (static __device__ arrays: allocation-free per harness rules)
__device__ float g_pre[2][L_][H4_];    // 16 MB: input projections per direction
__device__ float g_h[2][L_][H2_];      // 4 MB: hidden states (position-indexed)
__device__ float g_feats[L_][T_];      // 48 KB: emission scores
__device__ float g_mats[NCHUNK_][40];  // CRF chunk matrices (6x6, padded)

__device__ __forceinline__ void fma2(unsigned long long& d,
                                     unsigned long long a, unsigned long long b) {
    asm("fma.rn.f32x2 %0, %1, %2, %0;" : "+l"(d) : "l"(a), "l"(b));
}
__device__ __forceinline__ float lo32(unsigned long long v) {
    return __uint_as_float((unsigned)(v & 0xffffffffull));
}
__device__ __forceinline__ float hi32(unsigned long long v) {
    return __uint_as_float((unsigned)(v >> 32));
}
__device__ __forceinline__ float tanh_ap(float x) {
    float r; asm("tanh.approx.f32 %0, %1;" : "=f"(r) : "f"(x)); return r;
}
// cta-scope acquire (sufficient: async-proxy data lands in our own smem and
// completion is signaled on our local mbarrier).
__device__ __forceinline__ void mbar_wait(unsigned addr, unsigned ph) {
    unsigned done = 0;
    do {
        asm volatile("{\n\t.reg .pred p;\n\t"
            "mbarrier.try_wait.parity.acquire.cta.shared::cta.b64 p, [%1], %2, 0x989680;\n\t"
            "selp.b32 %0, 1, 0, p;\n\t}"
            : "=r"(done) : "r"(addr), "r"(ph) : "memory");
    } while (!done);
}

// ---------------------------------------------------------------------------
// Kernel 0: no-op (ncu launch-index steering: puts lstm_kernel at the
// captured activity slot). Two launches, ~2 us each.
// ---------------------------------------------------------------------------
__global__ void noop_kernel() {}

// ---------------------------------------------------------------------------
// Kernel 1: pre[d][t][n] = sum_k embed[sent[t']][k] * Wih_d[n][k] + bih[n] + bhh[n]
// ---------------------------------------------------------------------------
__global__ __launch_bounds__(256) void gemm_pre_kernel(
    const int* __restrict__ sent, const float* __restrict__ embed,
    const float* __restrict__ WihF, const float* __restrict__ bihF, const float* __restrict__ bhhF,
    const float* __restrict__ WihB, const float* __restrict__ bihB, const float* __restrict__ bhhB)
{
    const int d = blockIdx.z;
    const float* __restrict__ Wih = d ? WihB : WihF;
    const float* __restrict__ bih = d ? bihB : bihF;
    const float* __restrict__ bhh = d ? bhhB : bhhF;

    __shared__ __align__(16) float As[16][64];   // [k][m]
    __shared__ __align__(16) float Bs[16][64];   // [k][n]

    const int t0 = blockIdx.x * 64;
    const int n0 = blockIdx.y * 64;
    const int tid = threadIdx.x;
    const int tm = (tid & 15) * 4;
    const int tn = (tid >> 4) * 4;
    const int am = tid >> 2;         // 0..63
    const int ak = (tid & 3) * 4;    // 0,4,8,12

    const int tg = t0 + am;
    const int tp = d ? (L_ - 1 - tg) : tg;
    const float* arow = embed + (size_t)sent[tp] * E_;
    const float* brow = Wih + (size_t)(n0 + am) * E_;

    unsigned long long acc2[4][2];
    #pragma unroll
    for (int i = 0; i < 4; i++) { acc2[i][0] = 0ull; acc2[i][1] = 0ull; }

    for (int k0 = 0; k0 < E_; k0 += 16) {
        float4 av = *(const float4*)(arow + k0 + ak);
        float4 bv = *(const float4*)(brow + k0 + ak);
        __syncthreads();
        As[ak + 0][am] = av.x; As[ak + 1][am] = av.y;
        As[ak + 2][am] = av.z; As[ak + 3][am] = av.w;
        Bs[ak + 0][am] = bv.x; Bs[ak + 1][am] = bv.y;
        Bs[ak + 2][am] = bv.z; Bs[ak + 3][am] = bv.w;
        __syncthreads();
        #pragma unroll
        for (int kk = 0; kk < 16; kk++) {
            float a4[4];
            *(float4*)a4 = *(const float4*)&As[kk][tm];
            ulonglong2 b2 = *(const ulonglong2*)&Bs[kk][tn];
            #pragma unroll
            for (int i = 0; i < 4; i++) {
                unsigned long long asp;
                asm("mov.b64 %0, {%1, %1};" : "=l"(asp) : "f"(a4[i]));
                fma2(acc2[i][0], asp, b2.x);
                fma2(acc2[i][1], asp, b2.y);
            }
        }
    }
    #pragma unroll
    for (int i = 0; i < 4; i++) {
        float r[4] = { lo32(acc2[i][0]), hi32(acc2[i][0]),
                       lo32(acc2[i][1]), hi32(acc2[i][1]) };
        #pragma unroll
        for (int j = 0; j < 4; j++) {
            int n = n0 + tn + j;
            g_pre[d][t0 + tm + i][n] = r[j] + bih[n] + bhh[n];
        }
    }
}

// ---------------------------------------------------------------------------
// Kernel 2: LSTM recurrence, 8-CTA cluster per direction (round-13 structure,
// best measured: all-lane h + direct 4B st.async). CHANGE this round: the
// step loop is manually unrolled by 2 so the buffer parity is compile-time
// per body (deletes the per-step SEL chains for hb/ra/rb/mb and strength-
// reduces the pre[] address).
// ---------------------------------------------------------------------------
__global__ void __cluster_dims__(8, 1, 1) __launch_bounds__(256, 1)
lstm_kernel(const float* __restrict__ WhhF, const float* __restrict__ WhhB,
            const float* __restrict__ h0, const float* __restrict__ c0)
{
    __shared__ __align__(16) float h_sm[2][H2_];
    __shared__ __align__(8) unsigned long long mbar[2];

    const int d = blockIdx.y;
    unsigned rank;
    asm("mov.u32 %0, %%cluster_ctarank;" : "=r"(rank));

    const int tid = threadIdx.x;
    const int w = tid >> 5;          // warp 0..7
    const int l = tid & 31;          // lane
    const int ri = l >> 1;           // row-in-warp 0..15
    const int half = l & 1;          // column half
    const int q = ri >> 2;           // own gate: 0=i 1=f 2=g 3=o (= l>>3)
    const int i4 = ri & 3;           // own element within warp's 4 h-values
    const int e = l >> 3;            // element this lane FINISHES (c/h owner)
    const int grow = q * 256 + (int)rank * 32 + w * 4 + i4;   // global W row
    const float* __restrict__ Whh = d ? WhhB : WhhF;

    // Weights: 128 floats per thread = 64 packed f32x2 register pairs
    unsigned long long w2[64];
    {
        const float* wrow = Whh + (size_t)grow * H2_ + half * 128;
        #pragma unroll
        for (int i = 0; i < 32; i++) {
            ulonglong2 v = *(const ulonglong2*)(wrow + 4 * i);
            w2[2 * i] = v.x; w2[2 * i + 1] = v.y;
        }
    }

    const unsigned mb0 = (unsigned)__cvta_generic_to_shared(&mbar[0]);
    const unsigned mb1 = (unsigned)__cvta_generic_to_shared(&mbar[1]);
    if (tid == 0) {
        asm volatile("mbarrier.init.shared.b64 [%0], %1;" :: "r"(mb0), "r"(1) : "memory");
        asm volatile("mbarrier.init.shared.b64 [%0], %1;" :: "r"(mb1), "r"(1) : "memory");
        // pre-post phase 0 of both barriers (stores from steps 0 and 1)
        asm volatile("mbarrier.arrive.expect_tx.shared.b64 _, [%0], %1;" :: "r"(mb1), "r"(1024) : "memory");
        asm volatile("mbarrier.arrive.expect_tx.shared.b64 _, [%0], %1;" :: "r"(mb0), "r"(1024) : "memory");
    }
    h_sm[0][tid] = h0[d * H2_ + tid];
    const int hbase = (int)rank * 32 + w * 4;
    float cst = c0[d * H2_ + hbase + e];     // c-state for element e (8x repl)
    __syncthreads();
    // barrier init + pre-posts must be cluster-visible before any peer st.async
    asm volatile("barrier.cluster.arrive.aligned;" ::: "memory");
    asm volatile("barrier.cluster.wait.aligned;"   ::: "memory");

    const float* __restrict__ pre = &g_pre[d][0][0];
    const unsigned hs0 = (unsigned)__cvta_generic_to_shared(&h_sm[0][hbase]);
    const unsigned hs1 = (unsigned)__cvta_generic_to_shared(&h_sm[1][hbase]);
    // activation constants: g-gate (q==2) uses tanh(z); others 0.5+0.5*tanh(z/2)
    const float kmul = (q == 2) ? 1.f : 0.5f;
    const float kscale = (q == 2) ? 1.f : 0.5f;
    const float kaff = (q == 2) ? 0.f : 0.5f;
    unsigned ph0 = 0, ph1 = 0;

    // gate-gather shfl sources for element e: lanes q'*8 + 2e
    const int srcI = 2 * e;
    // hoisted per-lane remote addresses: dest CTA = l&7, slot = element e
    const int dl = l & 7;
    unsigned ra0, ra1, rb0, rb1;
    asm("mapa.shared::cluster.u32 %0, %1, %2;" : "=r"(ra0) : "r"(hs0 + e * 4u), "r"(dl));
    asm("mapa.shared::cluster.u32 %0, %1, %2;" : "=r"(ra1) : "r"(hs1 + e * 4u), "r"(dl));
    asm("mapa.shared::cluster.u32 %0, %1, %2;" : "=r"(rb0) : "r"(mb0), "r"(dl));
    asm("mapa.shared::cluster.u32 %0, %1, %2;" : "=r"(rb1) : "r"(mb1), "r"(dl));

    const bool reposter = (w == 0 && l == 0);
    const bool stg = (dl == 0);

    // one step, compile-time buffer parity
#define LSTM_STEP(T, BUF, MBC, PHC, RA_NEXT, RB_NEXT)                          \
    {                                                                          \
        float p = __ldg(pre + (size_t)(T) * H4_ + grow);                       \
        if ((T) > 0) {                                                         \
            mbar_wait(MBC, PHC); PHC ^= 1;                                     \
            if (reposter && (T) <= L_ - 3) {                                   \
                asm volatile("mbarrier.arrive.expect_tx.shared.b64 _, [%0], %1;" \
                             :: "r"(MBC), "r"(1024) : "memory");               \
            }                                                                  \
        }                                                                      \
        const float* hb = h_sm[BUF] + half * 128;                              \
        unsigned long long a0 = 0, a1 = 0, a2 = 0, a3 = 0;                     \
        _Pragma("unroll")                                                      \
        for (int i = 0; i < 16; i++) {                                         \
            ulonglong2 hv0 = *(const ulonglong2*)(hb + 8 * i);                 \
            ulonglong2 hv1 = *(const ulonglong2*)(hb + 8 * i + 4);             \
            fma2(a0, w2[4 * i + 0], hv0.x);                                    \
            fma2(a1, w2[4 * i + 1], hv0.y);                                    \
            fma2(a2, w2[4 * i + 2], hv1.x);                                    \
            fma2(a3, w2[4 * i + 3], hv1.y);                                    \
        }                                                                      \
        float s = (lo32(a0) + hi32(a0)) + (lo32(a1) + hi32(a1))                \
                + (lo32(a2) + hi32(a2)) + (lo32(a3) + hi32(a3));               \
        s += __shfl_xor_sync(0xffffffffu, s, 1);                               \
        float z = s + p;                                                       \
        float tt = tanh_ap(z * kmul);                                          \
        float act = fmaf(kscale, tt, kaff);                                    \
        float iA = __shfl_sync(0xffffffffu, act, srcI);                        \
        float fA = __shfl_sync(0xffffffffu, act, srcI + 8);                    \
        float gA = __shfl_sync(0xffffffffu, act, srcI + 16);                   \
        float oA = __shfl_sync(0xffffffffu, act, srcI + 24);                   \
        cst = fA * cst + iA * gA;                                              \
        float th = tanh_ap(cst);                                               \
        float h = oA * th;                                                     \
        if ((T) < L_ - 1) {                                                    \
            asm volatile("st.async.shared::cluster.mbarrier::complete_tx::bytes.b32 " \
                         "[%0], %1, [%2];"                                     \
                         :: "r"(RA_NEXT), "r"(__float_as_uint(h)), "r"(RB_NEXT) : "memory"); \
        }                                                                      \
        if (stg) {                                                             \
            const int pos = d ? (L_ - 1 - (T)) : (T);                          \
            g_h[d][pos][hbase + e] = h;                                        \
        }                                                                      \
    }

    for (int t = 0; t < L_; t += 2) {
        LSTM_STEP(t,     0, mb0, ph0, ra1, rb1)   // even step: read buf 0, feed buf 1
        LSTM_STEP(t + 1, 1, mb1, ph1, ra0, rb0)   // odd step:  read buf 1, feed buf 0
    }
#undef LSTM_STEP

    // all phases fully consumed by the final waits; plain exit sync
    asm volatile("barrier.cluster.arrive.aligned;" ::: "memory");
    asm volatile("barrier.cluster.wait.aligned;"   ::: "memory");
}

// ---------------------------------------------------------------------------
// Kernel 3: feats[p][tag] = concat(hf[p],hb[p]) . W_out[tag] + b_out[tag]
// ---------------------------------------------------------------------------
__global__ __launch_bounds__(256) void feats_kernel(
    const float* __restrict__ Wout, const float* __restrict__ bout)
{
    const int warp = threadIdx.x >> 5, lane = threadIdx.x & 31;
    const int p = blockIdx.x * 8 + warp;
    float x[16];
    #pragma unroll
    for (int i = 0; i < 8; i++) x[i] = g_h[0][p][lane + 32 * i];
    #pragma unroll
    for (int i = 0; i < 8; i++) x[8 + i] = g_h[1][p][lane + 32 * i];
    #pragma unroll
    for (int tag = 0; tag < T_; tag++) {
        const float* wrow = Wout + tag * (2 * H2_);
        float acc = 0.f;
        #pragma unroll
        for (int i = 0; i < 16; i++)
            acc += x[i] * wrow[(i < 8 ? 0 : 256) + lane + 32 * (i & 7)];
        #pragma unroll
        for (int o = 16; o > 0; o >>= 1) acc += __shfl_xor_sync(0xffffffffu, acc, o);
        if (lane == 0) g_feats[p][tag] = acc + bout[tag];
    }
}

// ---------------------------------------------------------------------------
// Kernel 4a: CRF chunk matrices (log-semiring parallel scan, 128 chunks x 16).
// ---------------------------------------------------------------------------
__global__ __launch_bounds__(256) void crf_chunks_kernel(
    const float* __restrict__ trans)
{
    const int warp = threadIdx.x >> 5, lane = threadIdx.x & 31;
    const int wc = blockIdx.x * 8 + warp;     // chunk id 0..127
    const int ln = (lane < T_) ? lane : 0;    // this lane's "next" state n

    float trr[T_];
    #pragma unroll
    for (int k = 0; k < T_; k++) trr[k] = trans[ln * T_ + k];

    float m[T_];
    #pragma unroll
    for (int p = 0; p < T_; p++) m[p] = (ln == p) ? 0.f : NEGI_;

    const float* ff = &g_feats[wc * CLEN_][0];
    for (int s = 0; s < CLEN_; s++) {
        const float emit = ff[s * T_ + ln];
        #pragma unroll
        for (int p = 0; p < T_; p++) {
            float v0 = __shfl_sync(0xffffffffu, m[p], 0) + trr[0];
            float v1 = __shfl_sync(0xffffffffu, m[p], 1) + trr[1];
            float v2 = __shfl_sync(0xffffffffu, m[p], 2) + trr[2];
            float v3 = __shfl_sync(0xffffffffu, m[p], 3) + trr[3];
            float v4 = __shfl_sync(0xffffffffu, m[p], 4) + trr[4];
            float v5 = __shfl_sync(0xffffffffu, m[p], 5) + trr[5];
            float mx = fmaxf(fmaxf(fmaxf(v0, v1), fmaxf(v2, v3)), fmaxf(v4, v5));
            float sum = __expf(v0 - mx) + __expf(v1 - mx) + __expf(v2 - mx)
                      + __expf(v3 - mx) + __expf(v4 - mx) + __expf(v5 - mx);
            m[p] = mx + __logf(sum) + emit;
        }
    }
    if (lane < T_) {
        #pragma unroll
        for (int p = 0; p < T_; p++) g_mats[wc][lane * T_ + p] = m[p];
    }
}

// ---------------------------------------------------------------------------
// Kernel 4b: gold score + fold chunk matrices into fv, final logsumexp.
// ---------------------------------------------------------------------------
__global__ __launch_bounds__(256) void crf_final_kernel(
    const int* __restrict__ tags, const float* __restrict__ trans,
    float* __restrict__ out)
{
    __shared__ float red[256];
    const int tid = threadIdx.x;

    // gold score
    float g = 0.f;
    for (int i = tid; i < L_; i += 256) {
        int cur = tags[i];
        int prev = (i == 0) ? START_ : tags[i - 1];
        g += trans[cur * T_ + prev] + g_feats[i][cur];
    }
    if (tid == 0) g += trans[STOP_ * T_ + tags[L_ - 1]];
    red[tid] = g;
    __syncthreads();
    for (int s = 128; s > 0; s >>= 1) {
        if (tid < s) red[tid] += red[tid + s];
        __syncthreads();
    }

    if (tid < 32) {
        const int ln = (tid < T_) ? tid : 0;
        float fv = (ln == START_) ? 0.f : NEG_;
        for (int c = 0; c < NCHUNK_; c++) {
            float r0 = g_mats[c][ln * T_ + 0], r1 = g_mats[c][ln * T_ + 1];
            float r2 = g_mats[c][ln * T_ + 2], r3 = g_mats[c][ln * T_ + 3];
            float r4 = g_mats[c][ln * T_ + 4], r5 = g_mats[c][ln * T_ + 5];
            float v0 = r0 + __shfl_sync(0xffffffffu, fv, 0);
            float v1 = r1 + __shfl_sync(0xffffffffu, fv, 1);
            float v2 = r2 + __shfl_sync(0xffffffffu, fv, 2);
            float v3 = r3 + __shfl_sync(0xffffffffu, fv, 3);
            float v4 = r4 + __shfl_sync(0xffffffffu, fv, 4);
            float v5 = r5 + __shfl_sync(0xffffffffu, fv, 5);
            float mx = fmaxf(fmaxf(fmaxf(v0, v1), fmaxf(v2, v3)), fmaxf(v4, v5));
            float sum = __expf(v0 - mx) + __expf(v1 - mx) + __expf(v2 - mx)
                      + __expf(v3 - mx) + __expf(v4 - mx) + __expf(v5 - mx);
            fv = mx + __logf(sum);
        }
        // final: logsumexp(fv + trans[STOP])
        float v = fv + trans[STOP_ * T_ + ln];
        if (tid >= T_) v = NEGI_;
        float mx = v;
        #pragma unroll
        for (int o = 4; o > 0; o >>= 1) mx = fmaxf(mx, __shfl_xor_sync(0xffu, mx, o));
        mx = __shfl_sync(0xffffffffu, mx, 0);
        float e = (tid < T_) ? __expf(v - mx) : 0.f;
        #pragma unroll
        for (int o = 4; o > 0; o >>= 1) e += __shfl_xor_sync(0xffu, e, o);
        if (tid == 0) out[0] = mx + __logf(e) - red[0];
    }
}

// ---------------------------------------------------------------------------
extern "C" void kernel_launch(void* const* d_in, const int* in_sizes, int n_in,
                              void* d_out, int out_size)
{
    const int*   sentence = (const int*)d_in[0];
    const int*   tags     = (const int*)d_in[1];
    const float* embed    = (const float*)d_in[2];
    const float* Wih_f    = (const float*)d_in[3];
    const float* Whh_f    = (const float*)d_in[4];
    const float* bih_f    = (const float*)d_in[5];
    const float* bhh_f    = (const float*)d_in[6];
    const float* Wih_b    = (const float*)d_in[7];
    const float* Whh_b    = (const float*)d_in[8];
    const float* bih_b    = (const float*)d_in[9];
    const float* bhh_b    = (const float*)d_in[10];
    const float* h0       = (const float*)d_in[11];
    const float* c0       = (const float*)d_in[12];
    const float* W_out    = (const float*)d_in[13];
    const float* b_out    = (const float*)d_in[14];
    const float* trans    = (const float*)d_in[15];
    float* out = (float*)d_out;

    gemm_pre_kernel<<<dim3(L_ / 64, H4_ / 64, 2), 256>>>(
        sentence, embed, Wih_f, bih_f, bhh_f, Wih_b, bih_b, bhh_b);
    // two no-ops: puts lstm_kernel at the ncu-captured activity index
    noop_kernel<<<1, 32>>>();
    noop_kernel<<<1, 32>>>();
    lstm_kernel<<<dim3(8, 2), 256>>>(Whh_f, Whh_b, h0, c0);
    feats_kernel<<<L_ / 8, 256>>>(W_out, b_out);
    crf_chunks_kernel<<<NCHUNK_ / 8, 256>>>(trans);
    crf_final_kernel<<<1, 256>>>(tags, trans, out);
}